// round 9
// baseline (speedup 1.0000x reference)
#include <cuda_runtime.h>
#include <math.h>

// Problem constants
#define HH 128
#define WW 128
#define BATCH 2
#define CFEAT 128
#define PLANE (HH * WW)
#define KDIM (9 * CFEAT)          // 1152

typedef unsigned long long ull;

// ---------------------------------------------------------------------------
// f32x2 packed-FMA helpers (SASS FFMA2 — PTX-only)
// ---------------------------------------------------------------------------
__device__ __forceinline__ void fma2(ull& d, ull a, ull b) {
    asm("fma.rn.f32x2 %0, %1, %2, %3;" : "=l"(d) : "l"(a), "l"(b), "l"(d));
}
__device__ __forceinline__ ull pack2(float lo, float hi) {
    ull r;
    asm("mov.b64 %0, {%1, %2};" : "=l"(r) : "f"(lo), "f"(hi));
    return r;
}
__device__ __forceinline__ void unpack2(ull v, float& lo, float& hi) {
    asm("mov.b64 {%0, %1}, %2;" : "=f"(lo), "=f"(hi) : "l"(v));
}

// ---------------------------------------------------------------------------
// cp.async helpers
// ---------------------------------------------------------------------------
__device__ __forceinline__ void cp16(void* smem, const void* gmem) {
    unsigned s = (unsigned)__cvta_generic_to_shared(smem);
    asm volatile("cp.async.cg.shared.global [%0], [%1], 16;" :: "r"(s), "l"(gmem));
}
__device__ __forceinline__ void cp_commit() {
    asm volatile("cp.async.commit_group;");
}
template <int N>
__device__ __forceinline__ void cp_wait() {
    asm volatile("cp.async.wait_group %0;" :: "n"(N));
}

// ---------------------------------------------------------------------------
// Scratch (device globals; no allocation allowed)
// ---------------------------------------------------------------------------
__device__ float g_tmp1[BATCH * 64 * PLANE];      // conv1 out  (B,64,H,W)
__device__ float g_off [BATCH * 18 * PLANE];      // offsets    (B,18,H,W)
__device__ float g_tmp2[BATCH * CFEAT * PLANE];   // deform out (B,128,H,W)
__device__ float g_tmp3[BATCH * 64 * PLANE];      // fh conv1   (B,64,H,W)
__device__ float g_dwt [KDIM * CFEAT];            // dweight transposed [kc][o]
__device__ float g_w1t [9 * 130 * 64];            // off_w1 transposed [kk][c][o]
__device__ float g_w3t [9 * 128 * 64];            // fh_w1  transposed [kk][c][o]
__device__ float g_samp[BATCH * KDIM * PLANE];    // bilinear samples [b][kc][px]

// ---------------------------------------------------------------------------
// Weight transposes
// ---------------------------------------------------------------------------
__global__ void wt_transpose_kernel(const float* __restrict__ dw) {
    int t = blockIdx.x * blockDim.x + threadIdx.x;
    if (t >= CFEAT * CFEAT * 9) return;
    int o  = t / (CFEAT * 9);
    int r  = t % (CFEAT * 9);
    int c  = r / 9;
    int kk = r % 9;
    g_dwt[(kk * CFEAT + c) * CFEAT + o] = dw[t];
}

__global__ void conv_wt_transpose_kernel(const float* __restrict__ w,
                                         float* __restrict__ dst, int cin) {
    int t = blockIdx.x * blockDim.x + threadIdx.x;
    if (t >= 64 * cin * 9) return;
    int o  = t / (cin * 9);
    int r  = t % (cin * 9);
    int c  = r / 9;
    int kk = r % 9;
    dst[(kk * cin + c) * 64 + o] = w[t];
}

// ---------------------------------------------------------------------------
// 3x3 SAME conv v4 (round-5 known-good): Cout=64 split into halves.
// ---------------------------------------------------------------------------
template <int CINA, int CINB, bool RELU>
__global__ __launch_bounds__(256)
void conv3x3_c64_kernel(const float* __restrict__ inA, const float* __restrict__ inB,
                        const float* __restrict__ wt, const float* __restrict__ bias,
                        float* __restrict__ out) {
    constexpr int CIN   = CINA + CINB;
    constexpr int CB    = 8;
    constexpr int NITER = (CIN + CB - 1) / CB;
    constexpr int NELI  = CB * 6 * 34;
    constexpr int NIN   = (NELI + 255) / 256;
    constexpr int NW    = (CB * 9 * 32) / 256;

    __shared__ float2 s_in[2][CB][6][34];
    __shared__ float  s_w [2][CB][9][32];

    const int tid   = threadIdx.x;
    const int wx    = tid & 31;
    const int og    = tid >> 5;
    const int wtile = blockIdx.x >> 1;
    const int ohalf = blockIdx.x & 1;
    const int w0 = wtile * 32;
    const int h0 = blockIdx.y * 4;
    const int b  = blockIdx.z;

    int in_cc[NIN], in_poff[NIN];
    bool in_ok[NIN];
#pragma unroll
    for (int s = 0; s < NIN; s++) {
        int i = tid + s * 256;
        in_cc[s] = 0; in_poff[s] = 0; in_ok[s] = false;
        if (i < NELI) {
            int cc  = i / 204;
            int rem = i % 204;
            int r   = rem / 34;
            int col = rem % 34;
            int y = h0 - 1 + r;
            int x = w0 - 1 + col;
            in_cc[s] = cc;
            if (y >= 0 && y < HH && x >= 0 && x < WW) {
                in_ok[s]   = true;
                in_poff[s] = y * WW + x;
            }
        }
    }
    int w_off[NW], w_cc[NW];
#pragma unroll
    for (int s = 0; s < NW; s++) {
        int i  = tid + s * 256;
        int oo = i & 31;
        int kk = (i >> 5) % 9;
        int cc = i / 288;
        w_cc[s]  = cc;
        w_off[s] = (kk * CIN + cc) * 64 + ohalf * 32 + oo;
    }

    float vin[NIN], vw[NW];

    auto ldg_chunk = [&](int it) {
        int c0 = it * CB;
#pragma unroll
        for (int s = 0; s < NIN; s++) {
            int c = c0 + in_cc[s];
            float v = 0.f;
            if (in_ok[s] && c < CIN) {
                if (CINB == 0 || c < CINA)
                    v = __ldg(&inA[(size_t)(b * CINA + c) * PLANE + in_poff[s]]);
                else
                    v = __ldg(&inB[(size_t)(b * CINB + (c - CINA)) * PLANE + in_poff[s]]);
            }
            vin[s] = v;
        }
#pragma unroll
        for (int s = 0; s < NW; s++) {
            int c = c0 + w_cc[s];
            vw[s] = (c < CIN) ? __ldg(&wt[(size_t)w_off[s] + (size_t)c0 * 64]) : 0.f;
        }
    };
    auto sts_chunk = [&](int buf) {
        float2* pi = &s_in[buf][0][0][0];
#pragma unroll
        for (int s = 0; s < NIN; s++) {
            int i = tid + s * 256;
            if (i < NELI) pi[i] = make_float2(vin[s], vin[s]);
        }
        float* pw = &s_w[buf][0][0][0];
#pragma unroll
        for (int s = 0; s < NW; s++) pw[tid + s * 256] = vw[s];
    };

    ull acc2[4][2];
#pragma unroll
    for (int i = 0; i < 4; i++) { acc2[i][0] = 0ULL; acc2[i][1] = 0ULL; }

    ldg_chunk(0);
    sts_chunk(0);
    __syncthreads();

    for (int it = 0; it < NITER; it++) {
        const int cur = it & 1;
        if (it + 1 < NITER) ldg_chunk(it + 1);

#pragma unroll
        for (int cc = 0; cc < CB; cc++) {
#pragma unroll
            for (int q = 0; q < 3; q++) {
                ull ad6[6];
#pragma unroll
                for (int r = 0; r < 6; r++)
                    ad6[r] = *(const ull*)&s_in[cur][cc][r][wx + q];
#pragma unroll
                for (int kh = 0; kh < 3; kh++) {
                    const ulonglong2 bb =
                        *(const ulonglong2*)&s_w[cur][cc][kh * 3 + q][og * 4];
#pragma unroll
                    for (int i = 0; i < 4; i++) {
                        fma2(acc2[i][0], ad6[i + kh], bb.x);
                        fma2(acc2[i][1], ad6[i + kh], bb.y);
                    }
                }
            }
        }

        if (it + 1 < NITER) sts_chunk(cur ^ 1);
        __syncthreads();
    }

#pragma unroll
    for (int j = 0; j < 2; j++) {
        int o0 = ohalf * 32 + og * 4 + 2 * j;
        float b0 = bias[o0];
        float b1 = bias[o0 + 1];
#pragma unroll
        for (int i = 0; i < 4; i++) {
            float lo, hi;
            unpack2(acc2[i][j], lo, hi);
            float v0 = lo + b0;
            float v1 = hi + b1;
            if (RELU) { v0 = fmaxf(v0, 0.f); v1 = fmaxf(v1, 0.f); }
            out[((b * 64 + o0)     * HH + (h0 + i)) * WW + w0 + wx] = v0;
            out[((b * 64 + o0 + 1) * HH + (h0 + i)) * WW + w0 + wx] = v1;
        }
    }
}

// ---------------------------------------------------------------------------
// 3x3 SAME conv, CIN=64, small Cout (<=18), optional residual add.
// ---------------------------------------------------------------------------
template <int COUT, bool RES>
__global__ __launch_bounds__(256)
void conv3x3_small_kernel(const float* __restrict__ in, const float* __restrict__ wgt,
                          const float* __restrict__ bias, const float* __restrict__ res,
                          float* __restrict__ out) {
    constexpr int CIN = 64;
    constexpr int CB = 4;
    __shared__ float s_in[CB][10][34];
    __shared__ float s_w[CB][COUT * 9];

    const int tid = threadIdx.x;
    const int wx = tid & 31;
    const int hy = tid >> 5;
    const int w0 = blockIdx.x * 32;
    const int h0 = blockIdx.y * 8;
    const int b  = blockIdx.z;

    float acc[COUT];
#pragma unroll
    for (int o = 0; o < COUT; o++) acc[o] = 0.f;

    for (int c0 = 0; c0 < CIN; c0 += CB) {
        for (int i = tid; i < CB * 10 * 34; i += 256) {
            int cc  = i / 340;
            int rem = i % 340;
            int r   = rem / 34;
            int col = rem % 34;
            int y = h0 - 1 + r;
            int x = w0 - 1 + col;
            float v = 0.f;
            if (y >= 0 && y < HH && x >= 0 && x < WW)
                v = in[((b * CIN + c0 + cc) * HH + y) * WW + x];
            s_in[cc][r][col] = v;
        }
        for (int i = tid; i < CB * COUT * 9; i += 256) {
            int cc  = i / (COUT * 9);
            int rem = i % (COUT * 9);
            int o   = rem / 9;
            int kk  = rem % 9;
            s_w[cc][rem] = wgt[(o * CIN + (c0 + cc)) * 9 + kk];
        }
        __syncthreads();

#pragma unroll
        for (int cc = 0; cc < CB; cc++) {
#pragma unroll
            for (int kh = 0; kh < 3; kh++) {
#pragma unroll
                for (int kw = 0; kw < 3; kw++) {
                    float iv = s_in[cc][hy + kh][wx + kw];
#pragma unroll
                    for (int o = 0; o < COUT; o++)
                        acc[o] += iv * s_w[cc][o * 9 + kh * 3 + kw];
                }
            }
        }
        __syncthreads();
    }

#pragma unroll
    for (int o = 0; o < COUT; o++) {
        float v = acc[o] + bias[o];
        int oi = ((b * COUT + o) * HH + (h0 + hy)) * WW + w0 + wx;
        if (RES) v += res[oi];
        out[oi] = v;
    }
}

// ---------------------------------------------------------------------------
// Gather kernel: bilinear samples for all (k, c, px) -> g_samp[b][k*128+c][px].
// Block = 256 px of one (b, k). Each thread: 1 px, loops all 128 channels.
// grid = (64, 9, B).
// ---------------------------------------------------------------------------
__global__ __launch_bounds__(256)
void gather_kernel(const float* __restrict__ feat, const float* __restrict__ offs) {
    const int tid = threadIdx.x;
    const int k  = blockIdx.y;
    const int b  = blockIdx.z;
    const int px = blockIdx.x * 256 + tid;
    const int h  = px >> 7;
    const int w  = px & 127;

    float offy = offs[(b * 18 + 2 * k)     * PLANE + px];
    float offx = offs[(b * 18 + 2 * k + 1) * PLANE + px];
    float fy = (float)(h + k / 3 - 1) + offy;
    float fx = (float)(w + k % 3 - 1) + offx;
    float y0f = floorf(fy), x0f = floorf(fx);
    float ly = fy - y0f, lx = fx - x0f;
    int y0 = (int)y0f, x0 = (int)x0f;

    float q[4] = {(1.f - ly) * (1.f - lx), (1.f - ly) * lx,
                  ly * (1.f - lx),          ly * lx};
    int ys[4] = {y0, y0, y0 + 1, y0 + 1};
    int xs[4] = {x0, x0 + 1, x0, x0 + 1};
    int idx[4];
#pragma unroll
    for (int c4 = 0; c4 < 4; c4++) {
        bool valid = (ys[c4] >= 0) && (ys[c4] < HH) && (xs[c4] >= 0) && (xs[c4] < WW);
        idx[c4] = valid ? (ys[c4] * WW + xs[c4]) : 0;
        if (!valid) q[c4] = 0.f;
    }

    const float* fbase = feat + (size_t)b * CFEAT * PLANE;
    float* obase = g_samp + ((size_t)(b * 9 + k) * CFEAT) * PLANE + px;

#pragma unroll 4
    for (int c = 0; c < CFEAT; c++) {
        const float* fc = fbase + (size_t)c * PLANE;
        obase[(size_t)c * PLANE] =
            q[0] * fc[idx[0]] + q[1] * fc[idx[1]] + q[2] * fc[idx[2]] + q[3] * fc[idx[3]];
    }
}

// ---------------------------------------------------------------------------
// Deform GEMM: out[b][o][px] = bias[o] + sum_kc w[kc][o] * samp[b][kc][px].
// CTA tile: 128 o x 128 px, K = 1152 in chunks of 32, cp.async double-buffered.
// 256 threads, per thread 8 px x 8 o (f32x2 over o pairs).
// DYNAMIC smem = 2 * (32*128 + 32*128) * 4 = 65536 B (needs opt-in attribute).
// grid = (128, 1, B).
// ---------------------------------------------------------------------------
#define DG_KC 32
#define DG_TILE (DG_KC * 128)                 // floats per tile (4096)
#define DGEMM_SMEM (2 * 2 * DG_TILE * 4)      // 65536 bytes

__global__ __launch_bounds__(256)
void dgemm_kernel(const float* __restrict__ dbias, float* __restrict__ out) {
    constexpr int KC  = DG_KC;
    constexpr int NCH = KDIM / KC;  // 36

    extern __shared__ float dsm[];
    // layout: [buf][ {w tile: KC*128} {s tile: KC*128} ]
    float* s_w[2] = {dsm,               dsm + 2 * DG_TILE};
    float* s_s[2] = {dsm + DG_TILE,     dsm + 3 * DG_TILE};

    const int tid = threadIdx.x;
    const int pxg = tid & 15;    // 16 groups of 8 px
    const int og  = tid >> 4;    // 16 groups of 8 o
    const int px0 = blockIdx.x * 128;
    const int b   = blockIdx.z;

    const float* wbase = g_dwt;
    const float* sbase = g_samp + (size_t)b * KDIM * PLANE + px0;

    // each thread stages 4 x 16B per tile per chunk
    const int srow = tid >> 3;          // 0..31 (row within chunk), 8 threads/row
    const int scol = (tid & 7) * 16;    // float offset within row

    auto load_chunk = [&](int ch, int buf) {
        int kc0 = ch * KC;
#pragma unroll
        for (int s = 0; s < 4; s++) {
            int col = scol + s * 4;
            cp16(&s_w[buf][srow * 128 + col], wbase + (size_t)(kc0 + srow) * 128 + col);
            cp16(&s_s[buf][srow * 128 + col], sbase + (size_t)(kc0 + srow) * PLANE + col);
        }
        cp_commit();
    };

    ull acc2[8][4];
#pragma unroll
    for (int i = 0; i < 8; i++)
#pragma unroll
        for (int j = 0; j < 4; j++) acc2[i][j] = 0ULL;

    load_chunk(0, 0);

    for (int ch = 0; ch < NCH; ch++) {
        const int cur = ch & 1;
        if (ch + 1 < NCH) {
            load_chunk(ch + 1, cur ^ 1);
            cp_wait<1>();
        } else {
            cp_wait<0>();
        }
        __syncthreads();

#pragma unroll 4
        for (int cc = 0; cc < KC; cc++) {
            const float4* ap = (const float4*)&s_s[cur][cc * 128 + pxg * 8];
            float4 a0 = ap[0];
            float4 a1 = ap[1];
            const ulonglong2* bp = (const ulonglong2*)&s_w[cur][cc * 128 + og * 8];
            ulonglong2 b01 = bp[0];
            ulonglong2 b23 = bp[1];
            ull bb[4] = {b01.x, b01.y, b23.x, b23.y};
            ull ad[8];
            ad[0] = pack2(a0.x, a0.x); ad[1] = pack2(a0.y, a0.y);
            ad[2] = pack2(a0.z, a0.z); ad[3] = pack2(a0.w, a0.w);
            ad[4] = pack2(a1.x, a1.x); ad[5] = pack2(a1.y, a1.y);
            ad[6] = pack2(a1.z, a1.z); ad[7] = pack2(a1.w, a1.w);
#pragma unroll
            for (int i = 0; i < 8; i++)
#pragma unroll
                for (int j = 0; j < 4; j++) fma2(acc2[i][j], ad[i], bb[j]);
        }
        __syncthreads();
    }

    // epilogue: o = og*8 + 2j (+1), px = px0 + pxg*8 + i
#pragma unroll
    for (int j = 0; j < 4; j++) {
        int o0 = og * 8 + 2 * j;
        float bv0 = dbias[o0];
        float bv1 = dbias[o0 + 1];
        float lo[8], hi[8];
#pragma unroll
        for (int i = 0; i < 8; i++) unpack2(acc2[i][j], lo[i], hi[i]);
        float* p0 = &out[((size_t)b * CFEAT + o0)     * PLANE + px0 + pxg * 8];
        float* p1 = &out[((size_t)b * CFEAT + o0 + 1) * PLANE + px0 + pxg * 8];
        ((float4*)p0)[0] = make_float4(lo[0] + bv0, lo[1] + bv0, lo[2] + bv0, lo[3] + bv0);
        ((float4*)p0)[1] = make_float4(lo[4] + bv0, lo[5] + bv0, lo[6] + bv0, lo[7] + bv0);
        ((float4*)p1)[0] = make_float4(hi[0] + bv1, hi[1] + bv1, hi[2] + bv1, hi[3] + bv1);
        ((float4*)p1)[1] = make_float4(hi[4] + bv1, hi[5] + bv1, hi[6] + bv1, hi[7] + bv1);
    }
}

// ---------------------------------------------------------------------------
// Launch
// ---------------------------------------------------------------------------
extern "C" void kernel_launch(void* const* d_in, const int* in_sizes, int n_in,
                              void* d_out, int out_size) {
    const float* feat    = (const float*)d_in[0];
    const float* flow    = (const float*)d_in[1];
    const float* off_w1  = (const float*)d_in[2];
    const float* off_b1  = (const float*)d_in[3];
    const float* off_w2  = (const float*)d_in[4];
    const float* off_b2  = (const float*)d_in[5];
    const float* dweight = (const float*)d_in[6];
    const float* dbias   = (const float*)d_in[7];
    const float* fh_w1   = (const float*)d_in[8];
    const float* fh_b1   = (const float*)d_in[9];
    const float* fh_w2   = (const float*)d_in[10];
    const float* fh_b2   = (const float*)d_in[11];
    float* out = (float*)d_out;

    float *tmp1, *off, *tmp2, *tmp3, *w1t, *w3t;
    cudaGetSymbolAddress((void**)&tmp1, g_tmp1);
    cudaGetSymbolAddress((void**)&off,  g_off);
    cudaGetSymbolAddress((void**)&tmp2, g_tmp2);
    cudaGetSymbolAddress((void**)&tmp3, g_tmp3);
    cudaGetSymbolAddress((void**)&w1t,  g_w1t);
    cudaGetSymbolAddress((void**)&w3t,  g_w3t);

    cudaFuncSetAttribute(dgemm_kernel, cudaFuncAttributeMaxDynamicSharedMemorySize,
                         DGEMM_SMEM);

    // 0. weight transposes
    wt_transpose_kernel<<<(CFEAT * CFEAT * 9 + 255) / 256, 256>>>(dweight);
    conv_wt_transpose_kernel<<<(64 * 130 * 9 + 255) / 256, 256>>>(off_w1, w1t, 130);
    conv_wt_transpose_kernel<<<(64 * 128 * 9 + 255) / 256, 256>>>(fh_w1, w3t, 128);

    // 1. conv1: concat(feat, flow) (130ch) -> 64ch, relu
    conv3x3_c64_kernel<128, 2, true><<<dim3(8, 32, BATCH), 256>>>(
        feat, flow, w1t, off_b1, tmp1);

    // 2. conv2: 64 -> 18 (offsets)
    conv3x3_small_kernel<18, false><<<dim3(4, 16, BATCH), 256>>>(
        tmp1, off_w2, off_b2, nullptr, off);

    // 3a. gather bilinear samples
    gather_kernel<<<dim3(64, 9, BATCH), 256>>>(feat, off);

    // 3b. deform GEMM
    dgemm_kernel<<<dim3(128, 1, BATCH), 256, DGEMM_SMEM>>>(dbias, tmp2);

    // 4. fh conv1: 128 -> 64, relu
    conv3x3_c64_kernel<128, 0, true><<<dim3(8, 32, BATCH), 256>>>(
        tmp2, tmp2, w3t, fh_b1, tmp3);

    // 5. fh conv2: 64 -> 2, + flow residual
    conv3x3_small_kernel<2, true><<<dim3(4, 16, BATCH), 256>>>(
        tmp3, fh_w2, fh_b2, flow, out);
}

// round 11
// speedup vs baseline: 1.1235x; 1.1235x over previous
#include <cuda_runtime.h>
#include <math.h>
#include <stdint.h>

// Problem constants
#define HH 128
#define WW 128
#define BATCH 2
#define CFEAT 128
#define PLANE (HH * WW)
#define KDIM (9 * CFEAT)          // 1152

typedef unsigned long long ull;

// ---------------------------------------------------------------------------
// f32x2 helpers (conv kernels)
// ---------------------------------------------------------------------------
__device__ __forceinline__ void fma2(ull& d, ull a, ull b) {
    asm("fma.rn.f32x2 %0, %1, %2, %3;" : "=l"(d) : "l"(a), "l"(b), "l"(d));
}
__device__ __forceinline__ void unpack2(ull v, float& lo, float& hi) {
    asm("mov.b64 {%0, %1}, %2;" : "=f"(lo), "=f"(hi) : "l"(v));
}

// ---------------------------------------------------------------------------
// cp.async / ldmatrix / mma.sync primitives (all sm_80-era, valid on sm_100)
// ---------------------------------------------------------------------------
__device__ __forceinline__ void cp16s(uint32_t smem, const void* gmem) {
    asm volatile("cp.async.cg.shared.global [%0], [%1], 16;" :: "r"(smem), "l"(gmem));
}
#define CP_COMMIT() asm volatile("cp.async.commit_group;")
template <int N>
__device__ __forceinline__ void cp_wait() {
    asm volatile("cp.async.wait_group %0;" :: "n"(N));
}

#define LDMX4(r, addr) \
    asm volatile("ldmatrix.sync.aligned.m8n8.x4.shared.b16 {%0,%1,%2,%3}, [%4];" \
                 : "=r"((r)[0]), "=r"((r)[1]), "=r"((r)[2]), "=r"((r)[3]) \
                 : "r"(addr))

__device__ __forceinline__ void mma_tf32_16n8k8(float* c, const uint32_t* a,
                                                uint32_t b0, uint32_t b1) {
    asm volatile(
        "mma.sync.aligned.m16n8k8.row.col.f32.tf32.tf32.f32 "
        "{%0,%1,%2,%3}, {%4,%5,%6,%7}, {%8,%9}, {%0,%1,%2,%3};"
        : "+f"(c[0]), "+f"(c[1]), "+f"(c[2]), "+f"(c[3])
        : "r"(a[0]), "r"(a[1]), "r"(a[2]), "r"(a[3]), "r"(b0), "r"(b1));
}

__device__ __forceinline__ float to_tf32(float x) {
    uint32_t u;
    asm("cvt.rna.tf32.f32 %0, %1;" : "=r"(u) : "f"(x));
    return __uint_as_float(u);
}

// ---------------------------------------------------------------------------
// Scratch (device globals; no allocation allowed)
// ---------------------------------------------------------------------------
__device__ float g_tmp1 [BATCH * 64 * PLANE];     // conv1 out  (B,64,H,W)
__device__ float g_off  [BATCH * 18 * PLANE];     // offsets    (B,18,H,W)
__device__ float g_tmp2 [BATCH * CFEAT * PLANE];  // deform out (B,128,H,W)
__device__ float g_tmp3 [BATCH * 64 * PLANE];     // fh conv1   (B,64,H,W)
__device__ float g_dwt2 [CFEAT * KDIM];           // dweight [o][k*128+c], tf32-rounded
__device__ float g_w1t  [9 * 130 * 64];           // off_w1 transposed [kk][c][o]
__device__ float g_w3t  [9 * 128 * 64];           // fh_w1  transposed [kk][c][o]
__device__ float g_sampT[BATCH * PLANE * KDIM];   // samples [b][px][k*128+c], tf32

// ---------------------------------------------------------------------------
// Weight transposes
// ---------------------------------------------------------------------------
__global__ void dwt2_transpose_kernel(const float* __restrict__ dw) {
    int t = blockIdx.x * blockDim.x + threadIdx.x;
    if (t >= CFEAT * KDIM) return;
    int o  = t / KDIM;
    int r  = t % KDIM;
    int c  = r / 9;
    int kk = r % 9;
    g_dwt2[(size_t)o * KDIM + kk * 128 + c] = to_tf32(dw[t]);
}

__global__ void conv_wt_transpose_kernel(const float* __restrict__ w,
                                         float* __restrict__ dst, int cin) {
    int t = blockIdx.x * blockDim.x + threadIdx.x;
    if (t >= 64 * cin * 9) return;
    int o  = t / (cin * 9);
    int r  = t % (cin * 9);
    int c  = r / 9;
    int kk = r % 9;
    dst[(kk * cin + c) * 64 + o] = w[t];
}

// ---------------------------------------------------------------------------
// 3x3 SAME conv (round-5 known-good): Cout=64 split into halves.
// ---------------------------------------------------------------------------
template <int CINA, int CINB, bool RELU>
__global__ __launch_bounds__(256)
void conv3x3_c64_kernel(const float* __restrict__ inA, const float* __restrict__ inB,
                        const float* __restrict__ wt, const float* __restrict__ bias,
                        float* __restrict__ out) {
    constexpr int CIN   = CINA + CINB;
    constexpr int CB    = 8;
    constexpr int NITER = (CIN + CB - 1) / CB;
    constexpr int NELI  = CB * 6 * 34;
    constexpr int NIN   = (NELI + 255) / 256;
    constexpr int NW    = (CB * 9 * 32) / 256;

    __shared__ float2 s_in[2][CB][6][34];
    __shared__ float  s_w [2][CB][9][32];

    const int tid   = threadIdx.x;
    const int wx    = tid & 31;
    const int og    = tid >> 5;
    const int wtile = blockIdx.x >> 1;
    const int ohalf = blockIdx.x & 1;
    const int w0 = wtile * 32;
    const int h0 = blockIdx.y * 4;
    const int b  = blockIdx.z;

    int in_cc[NIN], in_poff[NIN];
    bool in_ok[NIN];
#pragma unroll
    for (int s = 0; s < NIN; s++) {
        int i = tid + s * 256;
        in_cc[s] = 0; in_poff[s] = 0; in_ok[s] = false;
        if (i < NELI) {
            int cc  = i / 204;
            int rem = i % 204;
            int r   = rem / 34;
            int col = rem % 34;
            int y = h0 - 1 + r;
            int x = w0 - 1 + col;
            in_cc[s] = cc;
            if (y >= 0 && y < HH && x >= 0 && x < WW) {
                in_ok[s]   = true;
                in_poff[s] = y * WW + x;
            }
        }
    }
    int w_off[NW], w_cc[NW];
#pragma unroll
    for (int s = 0; s < NW; s++) {
        int i  = tid + s * 256;
        int oo = i & 31;
        int kk = (i >> 5) % 9;
        int cc = i / 288;
        w_cc[s]  = cc;
        w_off[s] = (kk * CIN + cc) * 64 + ohalf * 32 + oo;
    }

    float vin[NIN], vw[NW];

    auto ldg_chunk = [&](int it) {
        int c0 = it * CB;
#pragma unroll
        for (int s = 0; s < NIN; s++) {
            int c = c0 + in_cc[s];
            float v = 0.f;
            if (in_ok[s] && c < CIN) {
                if (CINB == 0 || c < CINA)
                    v = __ldg(&inA[(size_t)(b * CINA + c) * PLANE + in_poff[s]]);
                else
                    v = __ldg(&inB[(size_t)(b * CINB + (c - CINA)) * PLANE + in_poff[s]]);
            }
            vin[s] = v;
        }
#pragma unroll
        for (int s = 0; s < NW; s++) {
            int c = c0 + w_cc[s];
            vw[s] = (c < CIN) ? __ldg(&wt[(size_t)w_off[s] + (size_t)c0 * 64]) : 0.f;
        }
    };
    auto sts_chunk = [&](int buf) {
        float2* pi = &s_in[buf][0][0][0];
#pragma unroll
        for (int s = 0; s < NIN; s++) {
            int i = tid + s * 256;
            if (i < NELI) pi[i] = make_float2(vin[s], vin[s]);
        }
        float* pw = &s_w[buf][0][0][0];
#pragma unroll
        for (int s = 0; s < NW; s++) pw[tid + s * 256] = vw[s];
    };

    ull acc2[4][2];
#pragma unroll
    for (int i = 0; i < 4; i++) { acc2[i][0] = 0ULL; acc2[i][1] = 0ULL; }

    ldg_chunk(0);
    sts_chunk(0);
    __syncthreads();

    for (int it = 0; it < NITER; it++) {
        const int cur = it & 1;
        if (it + 1 < NITER) ldg_chunk(it + 1);

#pragma unroll
        for (int cc = 0; cc < CB; cc++) {
#pragma unroll
            for (int q = 0; q < 3; q++) {
                ull ad6[6];
#pragma unroll
                for (int r = 0; r < 6; r++)
                    ad6[r] = *(const ull*)&s_in[cur][cc][r][wx + q];
#pragma unroll
                for (int kh = 0; kh < 3; kh++) {
                    const ulonglong2 bb =
                        *(const ulonglong2*)&s_w[cur][cc][kh * 3 + q][og * 4];
#pragma unroll
                    for (int i = 0; i < 4; i++) {
                        fma2(acc2[i][0], ad6[i + kh], bb.x);
                        fma2(acc2[i][1], ad6[i + kh], bb.y);
                    }
                }
            }
        }

        if (it + 1 < NITER) sts_chunk(cur ^ 1);
        __syncthreads();
    }

#pragma unroll
    for (int j = 0; j < 2; j++) {
        int o0 = ohalf * 32 + og * 4 + 2 * j;
        float b0 = bias[o0];
        float b1 = bias[o0 + 1];
#pragma unroll
        for (int i = 0; i < 4; i++) {
            float lo, hi;
            unpack2(acc2[i][j], lo, hi);
            float v0 = lo + b0;
            float v1 = hi + b1;
            if (RELU) { v0 = fmaxf(v0, 0.f); v1 = fmaxf(v1, 0.f); }
            out[((b * 64 + o0)     * HH + (h0 + i)) * WW + w0 + wx] = v0;
            out[((b * 64 + o0 + 1) * HH + (h0 + i)) * WW + w0 + wx] = v1;
        }
    }
}

// ---------------------------------------------------------------------------
// 3x3 SAME conv, CIN=64, small Cout (<=18), optional residual add.
// ---------------------------------------------------------------------------
template <int COUT, bool RES>
__global__ __launch_bounds__(256)
void conv3x3_small_kernel(const float* __restrict__ in, const float* __restrict__ wgt,
                          const float* __restrict__ bias, const float* __restrict__ res,
                          float* __restrict__ out) {
    constexpr int CIN = 64;
    constexpr int CB = 4;
    __shared__ float s_in[CB][10][34];
    __shared__ float s_w[CB][COUT * 9];

    const int tid = threadIdx.x;
    const int wx = tid & 31;
    const int hy = tid >> 5;
    const int w0 = blockIdx.x * 32;
    const int h0 = blockIdx.y * 8;
    const int b  = blockIdx.z;

    float acc[COUT];
#pragma unroll
    for (int o = 0; o < COUT; o++) acc[o] = 0.f;

    for (int c0 = 0; c0 < CIN; c0 += CB) {
        for (int i = tid; i < CB * 10 * 34; i += 256) {
            int cc  = i / 340;
            int rem = i % 340;
            int r   = rem / 34;
            int col = rem % 34;
            int y = h0 - 1 + r;
            int x = w0 - 1 + col;
            float v = 0.f;
            if (y >= 0 && y < HH && x >= 0 && x < WW)
                v = in[((b * CIN + c0 + cc) * HH + y) * WW + x];
            s_in[cc][r][col] = v;
        }
        for (int i = tid; i < CB * COUT * 9; i += 256) {
            int cc  = i / (COUT * 9);
            int rem = i % (COUT * 9);
            int o   = rem / 9;
            int kk  = rem % 9;
            s_w[cc][rem] = wgt[(o * CIN + (c0 + cc)) * 9 + kk];
        }
        __syncthreads();

#pragma unroll
        for (int cc = 0; cc < CB; cc++) {
#pragma unroll
            for (int kh = 0; kh < 3; kh++) {
#pragma unroll
                for (int kw = 0; kw < 3; kw++) {
                    float iv = s_in[cc][hy + kh][wx + kw];
#pragma unroll
                    for (int o = 0; o < COUT; o++)
                        acc[o] += iv * s_w[cc][o * 9 + kh * 3 + kw];
                }
            }
        }
        __syncthreads();
    }

#pragma unroll
    for (int o = 0; o < COUT; o++) {
        float v = acc[o] + bias[o];
        int oi = ((b * COUT + o) * HH + (h0 + hy)) * WW + w0 + wx;
        if (RES) v += res[oi];
        out[oi] = v;
    }
}

// ---------------------------------------------------------------------------
// Gather (transposed out, tf32-rounded): -> g_sampT[b][px][k*128+c].
// Block = 64 px of one (b, k). grid = (256, 9, B).
// ---------------------------------------------------------------------------
__global__ __launch_bounds__(256)
void gather_t_kernel(const float* __restrict__ feat, const float* __restrict__ offs) {
    __shared__ float s[64][132];
    const int tid = threadIdx.x;
    const int pxt = tid & 63;
    const int cg  = tid >> 6;
    const int k   = blockIdx.y;
    const int b   = blockIdx.z;
    const int px0 = blockIdx.x * 64;
    const int px  = px0 + pxt;
    const int h   = px >> 7;
    const int w   = px & 127;

    float offy = offs[(b * 18 + 2 * k)     * PLANE + px];
    float offx = offs[(b * 18 + 2 * k + 1) * PLANE + px];
    float fy = (float)(h + k / 3 - 1) + offy;
    float fx = (float)(w + k % 3 - 1) + offx;
    float y0f = floorf(fy), x0f = floorf(fx);
    float ly = fy - y0f, lx = fx - x0f;
    int y0 = (int)y0f, x0 = (int)x0f;

    float q[4] = {(1.f - ly) * (1.f - lx), (1.f - ly) * lx,
                  ly * (1.f - lx),          ly * lx};
    int ys[4] = {y0, y0, y0 + 1, y0 + 1};
    int xs[4] = {x0, x0 + 1, x0, x0 + 1};
    int idx[4];
#pragma unroll
    for (int c4 = 0; c4 < 4; c4++) {
        bool valid = (ys[c4] >= 0) && (ys[c4] < HH) && (xs[c4] >= 0) && (xs[c4] < WW);
        idx[c4] = valid ? (ys[c4] * WW + xs[c4]) : 0;
        if (!valid) q[c4] = 0.f;
    }

    const float* fbase = feat + (size_t)b * CFEAT * PLANE;
#pragma unroll 4
    for (int j = 0; j < 32; j++) {
        int c = cg * 32 + j;
        const float* fc = fbase + (size_t)c * PLANE;
        s[pxt][c] = to_tf32(q[0] * fc[idx[0]] + q[1] * fc[idx[1]]
                          + q[2] * fc[idx[2]] + q[3] * fc[idx[3]]);
    }
    __syncthreads();

    const int r  = tid >> 2;
    const int qq = tid & 3;
    float* dst = g_sampT + ((size_t)(b * PLANE + px0 + r)) * KDIM + k * 128 + qq * 32;
    const float* src = &s[r][qq * 32];
#pragma unroll
    for (int i = 0; i < 8; i++)
        ((float4*)dst)[i] = ((const float4*)src)[i];
}

// ---------------------------------------------------------------------------
// Deform GEMM via mma.sync tf32 (tensor pipe without tcgen05/sm_100a).
// CTA: D[128 px x 128 o] = sampT[128 x 1152] * dwt2[128 x 1152]^T.
// 8 warps, each 64px x 32o = 4 m-tiles x 4 n-tiles of m16n8k8.
// K chunks of 32, cp.async double-buffered, padded smem rows (AP=36 floats)
// for conflict-free 16B-aligned ldmatrix. grid = (128, 1, B).
// ---------------------------------------------------------------------------
#define AP 36
#define TILE_F (128 * AP)                 // 4608 floats / tile
#define MM_SMEM (2 * 2 * TILE_F * 4)      // 73728 bytes

__global__ __launch_bounds__(256)
void dgemm_mma_kernel(const float* __restrict__ dbias, float* __restrict__ out) {
    constexpr int NCH = KDIM / 32;        // 36

    extern __shared__ float dsm[];
    const uint32_t sb = (uint32_t)__cvta_generic_to_shared(dsm);
    const uint32_t As_a[2] = {sb,                 sb + 2 * TILE_F * 4};
    const uint32_t Bs_a[2] = {sb + TILE_F * 4,    sb + 3 * TILE_F * 4};

    const int tid = threadIdx.x;
    const int lid = tid & 31;
    const int wid = tid >> 5;
    const int px0 = blockIdx.x * 128;
    const int b   = blockIdx.z;

    const float* abase = g_sampT + (size_t)(b * PLANE + px0) * KDIM;
    const int seg0 = tid * 4;   // 1024 segs per tile, 4 per thread

    auto load_chunk = [&](int ch, int buf) {
        const int kc0 = ch * 32;
#pragma unroll
        for (int i = 0; i < 4; i++) {
            int seg = seg0 + i;
            int row = seg >> 3;
            int s   = seg & 7;
            uint32_t doff = (uint32_t)(row * AP + s * 4) * 4;
            cp16s(As_a[buf] + doff, abase + (size_t)row * KDIM + kc0 + s * 4);
            cp16s(Bs_a[buf] + doff, g_dwt2 + (size_t)row * KDIM + kc0 + s * 4);
        }
        CP_COMMIT();
    };

    // warp tiling: wpx in {0,1} (64-px half), wo in 0..3 (32-o quarter)
    const int wpx = wid & 1;
    const int wo  = wid >> 1;
    // ldmatrix lane address offsets (floats)
    const int j = lid >> 3, i8 = lid & 7;
    const uint32_t aoff = (uint32_t)(((j & 1) * 8 + i8) * AP + (j >> 1) * 4) * 4;
    const uint32_t boff = (uint32_t)(((j >> 1) * 8 + i8) * AP + (j & 1) * 4) * 4;

    float c[4][4][4];
#pragma unroll
    for (int mt = 0; mt < 4; mt++)
#pragma unroll
        for (int nt = 0; nt < 4; nt++)
#pragma unroll
            for (int e = 0; e < 4; e++) c[mt][nt][e] = 0.f;

    load_chunk(0, 0);

    for (int ch = 0; ch < NCH; ch++) {
        const int cur = ch & 1;
        if (ch + 1 < NCH) {
            load_chunk(ch + 1, cur ^ 1);
            cp_wait<1>();
        } else {
            cp_wait<0>();
        }
        __syncthreads();

#pragma unroll
        for (int ks = 0; ks < 4; ks++) {
            const uint32_t kk4 = (uint32_t)(ks * 8) * 4;
            uint32_t a[4][4];
#pragma unroll
            for (int mt = 0; mt < 4; mt++) {
                uint32_t addr = As_a[cur] + (uint32_t)((wpx * 64 + mt * 16) * AP) * 4
                              + kk4 + aoff;
                LDMX4(a[mt], addr);
            }
            uint32_t bf[2][4];
#pragma unroll
            for (int g = 0; g < 2; g++) {
                uint32_t addr = Bs_a[cur] + (uint32_t)((wo * 32 + g * 16) * AP) * 4
                              + kk4 + boff;
                LDMX4(bf[g], addr);
            }
#pragma unroll
            for (int mt = 0; mt < 4; mt++)
#pragma unroll
                for (int nt = 0; nt < 4; nt++)
                    mma_tf32_16n8k8(c[mt][nt], a[mt],
                                    bf[nt >> 1][(nt & 1) * 2],
                                    bf[nt >> 1][(nt & 1) * 2 + 1]);
        }
        __syncthreads();
    }

    // Epilogue: regs -> smem [o][px] -> coalesced global rows (+bias).
    float* s_t = dsm;   // 64KB needed, tiles are dead
#pragma unroll
    for (int mt = 0; mt < 4; mt++)
#pragma unroll
        for (int nt = 0; nt < 4; nt++) {
            int pxb = wpx * 64 + mt * 16 + (lid >> 2);
            int ob  = wo * 32 + nt * 8 + (lid & 3) * 2;
            s_t[ob * 128 + pxb]           = c[mt][nt][0];
            s_t[(ob + 1) * 128 + pxb]     = c[mt][nt][1];
            s_t[ob * 128 + pxb + 8]       = c[mt][nt][2];
            s_t[(ob + 1) * 128 + pxb + 8] = c[mt][nt][3];
        }
    __syncthreads();
    {
        const int r = tid >> 1;
        const int h = tid & 1;
        const float bv = dbias[r];
        float* dst = out + ((size_t)(b * CFEAT + r)) * PLANE + px0 + h * 64;
        const float* src = s_t + r * 128 + h * 64;
#pragma unroll
        for (int i = 0; i < 16; i++) {
            float4 v = ((const float4*)src)[i];
            ((float4*)dst)[i] = make_float4(v.x + bv, v.y + bv, v.z + bv, v.w + bv);
        }
    }
}

// ---------------------------------------------------------------------------
// Launch
// ---------------------------------------------------------------------------
extern "C" void kernel_launch(void* const* d_in, const int* in_sizes, int n_in,
                              void* d_out, int out_size) {
    const float* feat    = (const float*)d_in[0];
    const float* flow    = (const float*)d_in[1];
    const float* off_w1  = (const float*)d_in[2];
    const float* off_b1  = (const float*)d_in[3];
    const float* off_w2  = (const float*)d_in[4];
    const float* off_b2  = (const float*)d_in[5];
    const float* dweight = (const float*)d_in[6];
    const float* dbias   = (const float*)d_in[7];
    const float* fh_w1   = (const float*)d_in[8];
    const float* fh_b1   = (const float*)d_in[9];
    const float* fh_w2   = (const float*)d_in[10];
    const float* fh_b2   = (const float*)d_in[11];
    float* out = (float*)d_out;

    float *tmp1, *off, *tmp2, *tmp3, *w1t, *w3t;
    cudaGetSymbolAddress((void**)&tmp1, g_tmp1);
    cudaGetSymbolAddress((void**)&off,  g_off);
    cudaGetSymbolAddress((void**)&tmp2, g_tmp2);
    cudaGetSymbolAddress((void**)&tmp3, g_tmp3);
    cudaGetSymbolAddress((void**)&w1t,  g_w1t);
    cudaGetSymbolAddress((void**)&w3t,  g_w3t);

    cudaFuncSetAttribute(dgemm_mma_kernel, cudaFuncAttributeMaxDynamicSharedMemorySize,
                         MM_SMEM);

    // 0. weight transposes
    dwt2_transpose_kernel<<<(CFEAT * KDIM + 255) / 256, 256>>>(dweight);
    conv_wt_transpose_kernel<<<(64 * 130 * 9 + 255) / 256, 256>>>(off_w1, w1t, 130);
    conv_wt_transpose_kernel<<<(64 * 128 * 9 + 255) / 256, 256>>>(fh_w1, w3t, 128);

    // 1. conv1: concat(feat, flow) (130ch) -> 64ch, relu
    conv3x3_c64_kernel<128, 2, true><<<dim3(8, 32, BATCH), 256>>>(
        feat, flow, w1t, off_b1, tmp1);

    // 2. conv2: 64 -> 18 (offsets)
    conv3x3_small_kernel<18, false><<<dim3(4, 16, BATCH), 256>>>(
        tmp1, off_w2, off_b2, nullptr, off);

    // 3a. gather bilinear samples (transposed, tf32-rounded)
    gather_t_kernel<<<dim3(256, 9, BATCH), 256>>>(feat, off);

    // 3b. deform GEMM on tensor cores via mma.sync tf32
    dgemm_mma_kernel<<<dim3(128, 1, BATCH), 256, MM_SMEM>>>(dbias, tmp2);

    // 4. fh conv1: 128 -> 64, relu
    conv3x3_c64_kernel<128, 0, true><<<dim3(8, 32, BATCH), 256>>>(
        tmp2, tmp2, w3t, fh_b1, tmp3);

    // 5. fh conv2: 64 -> 2, + flow residual
    conv3x3_small_kernel<2, true><<<dim3(4, 16, BATCH), 256>>>(
        tmp3, fh_w2, fh_b2, flow, out);
}

// round 12
// speedup vs baseline: 1.4002x; 1.2463x over previous
#include <cuda_runtime.h>
#include <math.h>
#include <stdint.h>

// Problem constants
#define HH 128
#define WW 128
#define BATCH 2
#define CFEAT 128
#define PLANE (HH * WW)
#define KDIM (9 * CFEAT)          // 1152

// ---------------------------------------------------------------------------
// cp.async / ldmatrix / mma.sync primitives (sm_80-era, valid on sm_100)
// ---------------------------------------------------------------------------
__device__ __forceinline__ void cp16s(uint32_t smem, const void* gmem) {
    asm volatile("cp.async.cg.shared.global [%0], [%1], 16;" :: "r"(smem), "l"(gmem));
}
// zero-fill variant: src_size = 0 -> 16 bytes of zeros (no read)
__device__ __forceinline__ void cp16z(uint32_t smem, const void* gmem, uint32_t n) {
    asm volatile("cp.async.cg.shared.global [%0], [%1], 16, %2;"
                 :: "r"(smem), "l"(gmem), "r"(n));
}
#define CP_COMMIT() asm volatile("cp.async.commit_group;")
template <int N>
__device__ __forceinline__ void cp_wait() {
    asm volatile("cp.async.wait_group %0;" :: "n"(N));
}

#define LDMX4(r, addr) \
    asm volatile("ldmatrix.sync.aligned.m8n8.x4.shared.b16 {%0,%1,%2,%3}, [%4];" \
                 : "=r"((r)[0]), "=r"((r)[1]), "=r"((r)[2]), "=r"((r)[3]) \
                 : "r"(addr))

__device__ __forceinline__ void mma_tf32_16n8k8(float* c, const uint32_t* a,
                                                uint32_t b0, uint32_t b1) {
    asm volatile(
        "mma.sync.aligned.m16n8k8.row.col.f32.tf32.tf32.f32 "
        "{%0,%1,%2,%3}, {%4,%5,%6,%7}, {%8,%9}, {%0,%1,%2,%3};"
        : "+f"(c[0]), "+f"(c[1]), "+f"(c[2]), "+f"(c[3])
        : "r"(a[0]), "r"(a[1]), "r"(a[2]), "r"(a[3]), "r"(b0), "r"(b1));
}

__device__ __forceinline__ float to_tf32(float x) {
    uint32_t u;
    asm("cvt.rna.tf32.f32 %0, %1;" : "=r"(u) : "f"(x));
    return __uint_as_float(u);
}

// ---------------------------------------------------------------------------
// Scratch (device globals; zero-initialized; no allocation allowed)
// ---------------------------------------------------------------------------
#define CPAD1 160
__device__ float g_tmp1 [BATCH * 64 * PLANE];      // conv1 out NCHW
__device__ float g_off  [BATCH * 18 * PLANE];      // offsets NCHW
__device__ float g_tmp2T[BATCH * PLANE * CFEAT];   // deform out [b][px][o] tf32
__device__ float g_tmp3 [BATCH * 64 * PLANE];      // fh conv1 out NCHW
__device__ float g_dwt2 [CFEAT * KDIM];            // dweight [o][k*128+c] tf32
__device__ float g_wc1  [9 * 64 * CPAD1];          // off_w1 [tap][o][c_pad] tf32
__device__ float g_wc3  [9 * 64 * CFEAT];          // fh_w1  [tap][o][c] tf32
__device__ float g_inT1 [BATCH * PLANE * CPAD1];   // concat(feat,flow)T tf32
__device__ float g_sampT[BATCH * PLANE * KDIM];    // samples [b][px][k*128+c] tf32

// ---------------------------------------------------------------------------
// Weight transposes
// ---------------------------------------------------------------------------
__global__ void dwt2_transpose_kernel(const float* __restrict__ dw) {
    int t = blockIdx.x * blockDim.x + threadIdx.x;
    if (t >= CFEAT * KDIM) return;
    int o  = t / KDIM;
    int r  = t % KDIM;
    int c  = r / 9;
    int kk = r % 9;
    g_dwt2[(size_t)o * KDIM + kk * 128 + c] = to_tf32(dw[t]);
}

// conv weights [64][cin][3][3] -> dst[tap][o][cpad] (tf32; pads stay zero-init)
__global__ void wcv_transpose_kernel(const float* __restrict__ w,
                                     float* __restrict__ dst, int cin, int cpad) {
    int t = blockIdx.x * blockDim.x + threadIdx.x;
    if (t >= 64 * cin * 9) return;
    int o  = t / (cin * 9);
    int r  = t % (cin * 9);
    int c  = r / 9;
    int kk = r % 9;
    dst[(kk * 64 + o) * cpad + c] = to_tf32(w[t]);
}

// ---------------------------------------------------------------------------
// catT: concat(feat[128], flow[2]) NCHW -> g_inT1[b][px][160] (tf32, zero pad)
// Block = 64 px. grid = (256, 1, B).
// ---------------------------------------------------------------------------
__global__ __launch_bounds__(256)
void catT_kernel(const float* __restrict__ feat, const float* __restrict__ flow) {
    __shared__ float s[64][164];
    const int tid = threadIdx.x;
    const int pxt = tid & 63;
    const int cg  = tid >> 6;       // 4 groups of 40 channels
    const int b   = blockIdx.z;
    const int px0 = blockIdx.x * 64;
    const int px  = px0 + pxt;

#pragma unroll 8
    for (int j = 0; j < 40; j++) {
        int c = cg * 40 + j;
        float v = 0.f;
        if (c < 128)      v = feat[(size_t)(b * 128 + c) * PLANE + px];
        else if (c < 130) v = flow[(size_t)(b * 2 + (c - 128)) * PLANE + px];
        s[pxt][c] = to_tf32(v);
    }
    __syncthreads();

    const int r = tid >> 2;
    const int q = tid & 3;
    float* dst = g_inT1 + (size_t)(b * PLANE + px0 + r) * CPAD1 + q * 40;
    const float* src = &s[r][q * 40];
#pragma unroll
    for (int i = 0; i < 10; i++)
        ((float4*)dst)[i] = ((const float4*)src)[i];
}

// ---------------------------------------------------------------------------
// conv3x3 via mma.sync tf32 (implicit GEMM).
// CTA = one image row: D[128 px][64 o] = sum_{tap,c} inT[(h+dh)*W + w+dw][c] *
// wt[tap][o][c]. Tap-shifted A tiles staged via cp.async with src_size=0
// zero-fill on invalid rows. 8 warps: wm=wid&3 (32px), wn=wid>>2 (32o).
// smem = 2*(128+64)*36*4 = 55296 B. grid = (HH, 1, B).
// ---------------------------------------------------------------------------
#define CAP 36
#define CONV_AF (128 * CAP)
#define CONV_BF (64 * CAP)
#define CONV_SMEM (2 * (CONV_AF + CONV_BF) * 4)   // 55296 B

template <int CPAD, bool RELU>
__global__ __launch_bounds__(256)
void conv_mma_kernel(const float* __restrict__ inT, const float* __restrict__ wt,
                     const float* __restrict__ bias, float* __restrict__ out) {
    constexpr int CPC = CPAD / 32;
    constexpr int NCH = 9 * CPC;

    extern __shared__ float dsm[];
    const uint32_t sb = (uint32_t)__cvta_generic_to_shared(dsm);
    const uint32_t As_a[2] = {sb, sb + (CONV_AF + CONV_BF) * 4};
    const uint32_t Bs_a[2] = {sb + CONV_AF * 4,
                              sb + (2 * CONV_AF + CONV_BF) * 4};

    const int tid = threadIdx.x;
    const int lid = tid & 31;
    const int wid = tid >> 5;
    const int h   = blockIdx.x;
    const int b   = blockIdx.z;

    auto load_chunk = [&](int lch, int buf) {
        const int tap = lch / CPC;
        const int c0  = (lch % CPC) * 32;
        const int dh  = tap / 3 - 1;
        const int dw  = tap % 3 - 1;
        const int h2  = h + dh;
        const bool vh = (h2 >= 0) && (h2 < HH);
        const int h2c = vh ? h2 : 0;
        const float* inrow = inT + (size_t)(b * PLANE + h2c * WW) * CPAD;
        // A: 4 segs/thread (1024 segs: row=seg>>3, s=seg&7)
#pragma unroll
        for (int i = 0; i < 4; i++) {
            int seg = tid * 4 + i;
            int row = seg >> 3;
            int s8  = seg & 7;
            int ws  = row + dw;
            bool v  = vh && (ws >= 0) && (ws < WW);
            int wsc = v ? ws : 0;
            cp16z(As_a[buf] + (uint32_t)(row * CAP + s8 * 4) * 4,
                  inrow + (size_t)wsc * CPAD + c0 + s8 * 4, v ? 16u : 0u);
        }
        // B: 2 segs/thread (512 segs: o=seg>>3, s=seg&7)
#pragma unroll
        for (int i = 0; i < 2; i++) {
            int seg = tid * 2 + i;
            int o   = seg >> 3;
            int s8  = seg & 7;
            cp16s(Bs_a[buf] + (uint32_t)(o * CAP + s8 * 4) * 4,
                  wt + (size_t)(tap * 64 + o) * CPAD + c0 + s8 * 4);
        }
        CP_COMMIT();
    };

    const int wm = wid & 3;       // 32-px quarter
    const int wn = wid >> 2;      // 32-o half
    const int j = lid >> 3, i8 = lid & 7;
    const uint32_t aoff = (uint32_t)(((j & 1) * 8 + i8) * CAP + (j >> 1) * 4) * 4;
    const uint32_t boff = (uint32_t)(((j >> 1) * 8 + i8) * CAP + (j & 1) * 4) * 4;

    float c[2][4][4];
#pragma unroll
    for (int mt = 0; mt < 2; mt++)
#pragma unroll
        for (int nt = 0; nt < 4; nt++)
#pragma unroll
            for (int e = 0; e < 4; e++) c[mt][nt][e] = 0.f;

    load_chunk(0, 0);

    for (int ch = 0; ch < NCH; ch++) {
        const int cur = ch & 1;
        if (ch + 1 < NCH) {
            load_chunk(ch + 1, cur ^ 1);
            cp_wait<1>();
        } else {
            cp_wait<0>();
        }
        __syncthreads();

#pragma unroll
        for (int ks = 0; ks < 4; ks++) {
            const uint32_t kk4 = (uint32_t)(ks * 8) * 4;
            uint32_t a[2][4];
#pragma unroll
            for (int mt = 0; mt < 2; mt++)
                LDMX4(a[mt], As_a[cur] + (uint32_t)((wm * 32 + mt * 16) * CAP) * 4
                             + kk4 + aoff);
            uint32_t bf[2][4];
#pragma unroll
            for (int g = 0; g < 2; g++)
                LDMX4(bf[g], Bs_a[cur] + (uint32_t)((wn * 32 + g * 16) * CAP) * 4
                             + kk4 + boff);
#pragma unroll
            for (int mt = 0; mt < 2; mt++)
#pragma unroll
                for (int nt = 0; nt < 4; nt++)
                    mma_tf32_16n8k8(c[mt][nt], a[mt],
                                    bf[nt >> 1][(nt & 1) * 2],
                                    bf[nt >> 1][(nt & 1) * 2 + 1]);
        }
        __syncthreads();
    }

    // Epilogue: frags -> smem [o][px] (stride 132) -> NCHW row + bias (+relu)
    float* s_t = dsm;
#pragma unroll
    for (int mt = 0; mt < 2; mt++)
#pragma unroll
        for (int nt = 0; nt < 4; nt++) {
            int px = wm * 32 + mt * 16 + (lid >> 2);
            int o  = wn * 32 + nt * 8 + (lid & 3) * 2;
            s_t[o * 132 + px]           = c[mt][nt][0];
            s_t[(o + 1) * 132 + px]     = c[mt][nt][1];
            s_t[o * 132 + px + 8]       = c[mt][nt][2];
            s_t[(o + 1) * 132 + px + 8] = c[mt][nt][3];
        }
    __syncthreads();
    {
        const int o = tid >> 2;
        const int q = tid & 3;
        const float bv = bias[o];
        float* dst = out + ((size_t)(b * 64 + o) * HH + h) * WW + q * 32;
        const float* src = s_t + o * 132 + q * 32;
#pragma unroll
        for (int i = 0; i < 8; i++) {
            float4 v = ((const float4*)src)[i];
            float4 r = make_float4(v.x + bv, v.y + bv, v.z + bv, v.w + bv);
            if (RELU) {
                r.x = fmaxf(r.x, 0.f); r.y = fmaxf(r.y, 0.f);
                r.z = fmaxf(r.z, 0.f); r.w = fmaxf(r.w, 0.f);
            }
            ((float4*)dst)[i] = r;
        }
    }
}

// ---------------------------------------------------------------------------
// 3x3 SAME conv, CIN=64, small Cout (<=18), optional residual (known-good).
// ---------------------------------------------------------------------------
template <int COUT, bool RES>
__global__ __launch_bounds__(256)
void conv3x3_small_kernel(const float* __restrict__ in, const float* __restrict__ wgt,
                          const float* __restrict__ bias, const float* __restrict__ res,
                          float* __restrict__ out) {
    constexpr int CIN = 64;
    constexpr int CB = 4;
    __shared__ float s_in[CB][10][34];
    __shared__ float s_w[CB][COUT * 9];

    const int tid = threadIdx.x;
    const int wx = tid & 31;
    const int hy = tid >> 5;
    const int w0 = blockIdx.x * 32;
    const int h0 = blockIdx.y * 8;
    const int b  = blockIdx.z;

    float acc[COUT];
#pragma unroll
    for (int o = 0; o < COUT; o++) acc[o] = 0.f;

    for (int c0 = 0; c0 < CIN; c0 += CB) {
        for (int i = tid; i < CB * 10 * 34; i += 256) {
            int cc  = i / 340;
            int rem = i % 340;
            int r   = rem / 34;
            int col = rem % 34;
            int y = h0 - 1 + r;
            int x = w0 - 1 + col;
            float v = 0.f;
            if (y >= 0 && y < HH && x >= 0 && x < WW)
                v = in[((b * CIN + c0 + cc) * HH + y) * WW + x];
            s_in[cc][r][col] = v;
        }
        for (int i = tid; i < CB * COUT * 9; i += 256) {
            int cc  = i / (COUT * 9);
            int rem = i % (COUT * 9);
            int o   = rem / 9;
            int kk  = rem % 9;
            s_w[cc][rem] = wgt[(o * CIN + (c0 + cc)) * 9 + kk];
        }
        __syncthreads();

#pragma unroll
        for (int cc = 0; cc < CB; cc++) {
#pragma unroll
            for (int kh = 0; kh < 3; kh++) {
#pragma unroll
                for (int kw = 0; kw < 3; kw++) {
                    float iv = s_in[cc][hy + kh][wx + kw];
#pragma unroll
                    for (int o = 0; o < COUT; o++)
                        acc[o] += iv * s_w[cc][o * 9 + kh * 3 + kw];
                }
            }
        }
        __syncthreads();
    }

#pragma unroll
    for (int o = 0; o < COUT; o++) {
        float v = acc[o] + bias[o];
        int oi = ((b * COUT + o) * HH + (h0 + hy)) * WW + w0 + wx;
        if (RES) v += res[oi];
        out[oi] = v;
    }
}

// ---------------------------------------------------------------------------
// Gather (transposed, tf32): -> g_sampT[b][px][k*128+c]. grid = (256, 9, B).
// ---------------------------------------------------------------------------
__global__ __launch_bounds__(256)
void gather_t_kernel(const float* __restrict__ feat, const float* __restrict__ offs) {
    __shared__ float s[64][132];
    const int tid = threadIdx.x;
    const int pxt = tid & 63;
    const int cg  = tid >> 6;
    const int k   = blockIdx.y;
    const int b   = blockIdx.z;
    const int px0 = blockIdx.x * 64;
    const int px  = px0 + pxt;
    const int h   = px >> 7;
    const int w   = px & 127;

    float offy = offs[(b * 18 + 2 * k)     * PLANE + px];
    float offx = offs[(b * 18 + 2 * k + 1) * PLANE + px];
    float fy = (float)(h + k / 3 - 1) + offy;
    float fx = (float)(w + k % 3 - 1) + offx;
    float y0f = floorf(fy), x0f = floorf(fx);
    float ly = fy - y0f, lx = fx - x0f;
    int y0 = (int)y0f, x0 = (int)x0f;

    float q[4] = {(1.f - ly) * (1.f - lx), (1.f - ly) * lx,
                  ly * (1.f - lx),          ly * lx};
    int ys[4] = {y0, y0, y0 + 1, y0 + 1};
    int xs[4] = {x0, x0 + 1, x0, x0 + 1};
    int idx[4];
#pragma unroll
    for (int c4 = 0; c4 < 4; c4++) {
        bool valid = (ys[c4] >= 0) && (ys[c4] < HH) && (xs[c4] >= 0) && (xs[c4] < WW);
        idx[c4] = valid ? (ys[c4] * WW + xs[c4]) : 0;
        if (!valid) q[c4] = 0.f;
    }

    const float* fbase = feat + (size_t)b * CFEAT * PLANE;
#pragma unroll 4
    for (int j = 0; j < 32; j++) {
        int c = cg * 32 + j;
        const float* fc = fbase + (size_t)c * PLANE;
        s[pxt][c] = to_tf32(q[0] * fc[idx[0]] + q[1] * fc[idx[1]]
                          + q[2] * fc[idx[2]] + q[3] * fc[idx[3]]);
    }
    __syncthreads();

    const int r  = tid >> 2;
    const int qq = tid & 3;
    float* dst = g_sampT + ((size_t)(b * PLANE + px0 + r)) * KDIM + k * 128 + qq * 32;
    const float* src = &s[r][qq * 32];
#pragma unroll
    for (int i = 0; i < 8; i++)
        ((float4*)dst)[i] = ((const float4*)src)[i];
}

// ---------------------------------------------------------------------------
// Deform GEMM via mma.sync tf32 (round-11 proven). Epilogue now writes ONLY
// the transposed tf32 layout g_tmp2T[b][px][o] (+bias) for fh1's mma conv.
// grid = (128, 1, B).
// ---------------------------------------------------------------------------
#define AP 36
#define TILE_F (128 * AP)
#define MM_SMEM (2 * 2 * TILE_F * 4)      // 73728 bytes

__global__ __launch_bounds__(256)
void dgemm_mma_kernel(const float* __restrict__ dbias) {
    constexpr int NCH = KDIM / 32;        // 36

    extern __shared__ float dsm[];
    const uint32_t sb = (uint32_t)__cvta_generic_to_shared(dsm);
    const uint32_t As_a[2] = {sb,              sb + 2 * TILE_F * 4};
    const uint32_t Bs_a[2] = {sb + TILE_F * 4, sb + 3 * TILE_F * 4};

    const int tid = threadIdx.x;
    const int lid = tid & 31;
    const int wid = tid >> 5;
    const int px0 = blockIdx.x * 128;
    const int b   = blockIdx.z;

    const float* abase = g_sampT + (size_t)(b * PLANE + px0) * KDIM;
    const int seg0 = tid * 4;

    auto load_chunk = [&](int ch, int buf) {
        const int kc0 = ch * 32;
#pragma unroll
        for (int i = 0; i < 4; i++) {
            int seg = seg0 + i;
            int row = seg >> 3;
            int s   = seg & 7;
            uint32_t doff = (uint32_t)(row * AP + s * 4) * 4;
            cp16s(As_a[buf] + doff, abase + (size_t)row * KDIM + kc0 + s * 4);
            cp16s(Bs_a[buf] + doff, g_dwt2 + (size_t)row * KDIM + kc0 + s * 4);
        }
        CP_COMMIT();
    };

    const int wpx = wid & 1;
    const int wo  = wid >> 1;
    const int j = lid >> 3, i8 = lid & 7;
    const uint32_t aoff = (uint32_t)(((j & 1) * 8 + i8) * AP + (j >> 1) * 4) * 4;
    const uint32_t boff = (uint32_t)(((j >> 1) * 8 + i8) * AP + (j & 1) * 4) * 4;

    float c[4][4][4];
#pragma unroll
    for (int mt = 0; mt < 4; mt++)
#pragma unroll
        for (int nt = 0; nt < 4; nt++)
#pragma unroll
            for (int e = 0; e < 4; e++) c[mt][nt][e] = 0.f;

    load_chunk(0, 0);

    for (int ch = 0; ch < NCH; ch++) {
        const int cur = ch & 1;
        if (ch + 1 < NCH) {
            load_chunk(ch + 1, cur ^ 1);
            cp_wait<1>();
        } else {
            cp_wait<0>();
        }
        __syncthreads();

#pragma unroll
        for (int ks = 0; ks < 4; ks++) {
            const uint32_t kk4 = (uint32_t)(ks * 8) * 4;
            uint32_t a[4][4];
#pragma unroll
            for (int mt = 0; mt < 4; mt++)
                LDMX4(a[mt], As_a[cur] + (uint32_t)((wpx * 64 + mt * 16) * AP) * 4
                             + kk4 + aoff);
            uint32_t bf[2][4];
#pragma unroll
            for (int g = 0; g < 2; g++)
                LDMX4(bf[g], Bs_a[cur] + (uint32_t)((wo * 32 + g * 16) * AP) * 4
                             + kk4 + boff);
#pragma unroll
            for (int mt = 0; mt < 4; mt++)
#pragma unroll
                for (int nt = 0; nt < 4; nt++)
                    mma_tf32_16n8k8(c[mt][nt], a[mt],
                                    bf[nt >> 1][(nt & 1) * 2],
                                    bf[nt >> 1][(nt & 1) * 2 + 1]);
        }
        __syncthreads();
    }

    // Epilogue: frags (+bias, tf32) -> smem [px][o] (stride 132) -> g_tmp2T rows
    float* s_t = dsm;
#pragma unroll
    for (int mt = 0; mt < 4; mt++)
#pragma unroll
        for (int nt = 0; nt < 4; nt++) {
            int pxb = wpx * 64 + mt * 16 + (lid >> 2);
            int ob  = wo * 32 + nt * 8 + (lid & 3) * 2;
            float b0 = __ldg(&dbias[ob]);
            float b1 = __ldg(&dbias[ob + 1]);
            s_t[pxb * 132 + ob]           = to_tf32(c[mt][nt][0] + b0);
            s_t[pxb * 132 + ob + 1]       = to_tf32(c[mt][nt][1] + b1);
            s_t[(pxb + 8) * 132 + ob]     = to_tf32(c[mt][nt][2] + b0);
            s_t[(pxb + 8) * 132 + ob + 1] = to_tf32(c[mt][nt][3] + b1);
        }
    __syncthreads();
    {
        const int px = tid >> 1;
        const int hf = tid & 1;
        float* dst = g_tmp2T + (size_t)(b * PLANE + px0 + px) * CFEAT + hf * 64;
        const float* src = s_t + px * 132 + hf * 64;
#pragma unroll
        for (int i = 0; i < 16; i++)
            ((float4*)dst)[i] = ((const float4*)src)[i];
    }
}

// ---------------------------------------------------------------------------
// Launch
// ---------------------------------------------------------------------------
extern "C" void kernel_launch(void* const* d_in, const int* in_sizes, int n_in,
                              void* d_out, int out_size) {
    const float* feat    = (const float*)d_in[0];
    const float* flow    = (const float*)d_in[1];
    const float* off_w1  = (const float*)d_in[2];
    const float* off_b1  = (const float*)d_in[3];
    const float* off_w2  = (const float*)d_in[4];
    const float* off_b2  = (const float*)d_in[5];
    const float* dweight = (const float*)d_in[6];
    const float* dbias   = (const float*)d_in[7];
    const float* fh_w1   = (const float*)d_in[8];
    const float* fh_b1   = (const float*)d_in[9];
    const float* fh_w2   = (const float*)d_in[10];
    const float* fh_b2   = (const float*)d_in[11];
    float* out = (float*)d_out;

    float *tmp1, *off, *tmp2T, *tmp3, *wc1, *wc3, *inT1;
    cudaGetSymbolAddress((void**)&tmp1,  g_tmp1);
    cudaGetSymbolAddress((void**)&off,   g_off);
    cudaGetSymbolAddress((void**)&tmp2T, g_tmp2T);
    cudaGetSymbolAddress((void**)&tmp3,  g_tmp3);
    cudaGetSymbolAddress((void**)&wc1,   g_wc1);
    cudaGetSymbolAddress((void**)&wc3,   g_wc3);
    cudaGetSymbolAddress((void**)&inT1,  g_inT1);

    cudaFuncSetAttribute(dgemm_mma_kernel, cudaFuncAttributeMaxDynamicSharedMemorySize,
                         MM_SMEM);
    cudaFuncSetAttribute(conv_mma_kernel<CPAD1, true>,
                         cudaFuncAttributeMaxDynamicSharedMemorySize, CONV_SMEM);
    cudaFuncSetAttribute(conv_mma_kernel<CFEAT, true>,
                         cudaFuncAttributeMaxDynamicSharedMemorySize, CONV_SMEM);

    // 0. weight transposes (tf32)
    dwt2_transpose_kernel<<<(CFEAT * KDIM + 255) / 256, 256>>>(dweight);
    wcv_transpose_kernel<<<(64 * 130 * 9 + 255) / 256, 256>>>(off_w1, wc1, 130, CPAD1);
    wcv_transpose_kernel<<<(64 * 128 * 9 + 255) / 256, 256>>>(fh_w1, wc3, 128, CFEAT);

    // 1a. transpose concat(feat, flow) -> inT1 [px][160]
    catT_kernel<<<dim3(PLANE / 64, 1, BATCH), 256>>>(feat, flow);

    // 1b. conv1 via mma: 130 -> 64, relu (NCHW out)
    conv_mma_kernel<CPAD1, true><<<dim3(HH, 1, BATCH), 256, CONV_SMEM>>>(
        inT1, wc1, off_b1, tmp1);

    // 2. conv2: 64 -> 18 (offsets)
    conv3x3_small_kernel<18, false><<<dim3(4, 16, BATCH), 256>>>(
        tmp1, off_w2, off_b2, nullptr, off);

    // 3a. gather bilinear samples (transposed, tf32)
    gather_t_kernel<<<dim3(256, 9, BATCH), 256>>>(feat, off);

    // 3b. deform GEMM via mma -> tmp2T [px][o] (tf32, +bias)
    dgemm_mma_kernel<<<dim3(128, 1, BATCH), 256, MM_SMEM>>>(dbias);

    // 4. fh conv1 via mma: 128 -> 64, relu (reads tmp2T directly)
    conv_mma_kernel<CFEAT, true><<<dim3(HH, 1, BATCH), 256, CONV_SMEM>>>(
        tmp2T, wc3, fh_b1, tmp3);

    // 5. fh conv2: 64 -> 2, + flow residual
    conv3x3_small_kernel<2, true><<<dim3(4, 16, BATCH), 256>>>(
        tmp3, fh_w2, fh_b2, flow, out);
}

// round 13
// speedup vs baseline: 1.6326x; 1.1660x over previous
#include <cuda_runtime.h>
#include <math.h>
#include <stdint.h>

// Problem constants
#define HH 128
#define WW 128
#define BATCH 2
#define CFEAT 128
#define PLANE (HH * WW)
#define KDIM (9 * CFEAT)          // 1152

// ---------------------------------------------------------------------------
// cp.async / ldmatrix / mma.sync primitives (sm_80-era, valid on sm_100)
// ---------------------------------------------------------------------------
__device__ __forceinline__ void cp16s(uint32_t smem, const void* gmem) {
    asm volatile("cp.async.cg.shared.global [%0], [%1], 16;" :: "r"(smem), "l"(gmem));
}
__device__ __forceinline__ void cp16z(uint32_t smem, const void* gmem, uint32_t n) {
    asm volatile("cp.async.cg.shared.global [%0], [%1], 16, %2;"
                 :: "r"(smem), "l"(gmem), "r"(n));
}
#define CP_COMMIT() asm volatile("cp.async.commit_group;")
template <int N>
__device__ __forceinline__ void cp_wait() {
    asm volatile("cp.async.wait_group %0;" :: "n"(N));
}

#define LDMX4(r, addr) \
    asm volatile("ldmatrix.sync.aligned.m8n8.x4.shared.b16 {%0,%1,%2,%3}, [%4];" \
                 : "=r"((r)[0]), "=r"((r)[1]), "=r"((r)[2]), "=r"((r)[3]) \
                 : "r"(addr))

__device__ __forceinline__ void mma_tf32_16n8k8(float* c, const uint32_t* a,
                                                uint32_t b0, uint32_t b1) {
    asm volatile(
        "mma.sync.aligned.m16n8k8.row.col.f32.tf32.tf32.f32 "
        "{%0,%1,%2,%3}, {%4,%5,%6,%7}, {%8,%9}, {%0,%1,%2,%3};"
        : "+f"(c[0]), "+f"(c[1]), "+f"(c[2]), "+f"(c[3])
        : "r"(a[0]), "r"(a[1]), "r"(a[2]), "r"(a[3]), "r"(b0), "r"(b1));
}

__device__ __forceinline__ float to_tf32(float x) {
    uint32_t u;
    asm("cvt.rna.tf32.f32 %0, %1;" : "=r"(u) : "f"(x));
    return __uint_as_float(u);
}

// ---------------------------------------------------------------------------
// Scratch (device globals; zero-initialized; no allocation allowed)
// ---------------------------------------------------------------------------
#define CPAD1 160
__device__ float g_tmp1 [BATCH * 64 * PLANE];      // conv1 out NCHW
__device__ float g_off  [BATCH * 18 * PLANE];      // offsets NCHW
__device__ float g_tmp2T[BATCH * PLANE * CFEAT];   // deform out [b][px][o] tf32
__device__ float g_tmp3 [BATCH * 64 * PLANE];      // fh conv1 out NCHW
__device__ float g_dwt2 [CFEAT * KDIM];            // dweight [o][k*128+c] tf32
__device__ float g_wc1  [9 * 64 * CPAD1];          // off_w1 [tap][o][c_pad] tf32
__device__ float g_wc3  [9 * 64 * CFEAT];          // fh_w1  [tap][o][c] tf32
__device__ float g_inT1 [BATCH * PLANE * CPAD1];   // concat(feat,flow)T tf32

// ---------------------------------------------------------------------------
// Weight transposes
// ---------------------------------------------------------------------------
__global__ void dwt2_transpose_kernel(const float* __restrict__ dw) {
    int t = blockIdx.x * blockDim.x + threadIdx.x;
    if (t >= CFEAT * KDIM) return;
    int o  = t / KDIM;
    int r  = t % KDIM;
    int c  = r / 9;
    int kk = r % 9;
    g_dwt2[(size_t)o * KDIM + kk * 128 + c] = to_tf32(dw[t]);
}

__global__ void wcv_transpose_kernel(const float* __restrict__ w,
                                     float* __restrict__ dst, int cin, int cpad) {
    int t = blockIdx.x * blockDim.x + threadIdx.x;
    if (t >= 64 * cin * 9) return;
    int o  = t / (cin * 9);
    int r  = t % (cin * 9);
    int c  = r / 9;
    int kk = r % 9;
    dst[(kk * 64 + o) * cpad + c] = to_tf32(w[t]);
}

// ---------------------------------------------------------------------------
// catT: concat(feat[128], flow[2]) NCHW -> g_inT1[b][px][160] (tf32, zero pad)
// ---------------------------------------------------------------------------
__global__ __launch_bounds__(256)
void catT_kernel(const float* __restrict__ feat, const float* __restrict__ flow) {
    __shared__ float s[64][164];
    const int tid = threadIdx.x;
    const int pxt = tid & 63;
    const int cg  = tid >> 6;
    const int b   = blockIdx.z;
    const int px0 = blockIdx.x * 64;
    const int px  = px0 + pxt;

#pragma unroll 8
    for (int j = 0; j < 40; j++) {
        int c = cg * 40 + j;
        float v = 0.f;
        if (c < 128)      v = feat[(size_t)(b * 128 + c) * PLANE + px];
        else if (c < 130) v = flow[(size_t)(b * 2 + (c - 128)) * PLANE + px];
        s[pxt][c] = to_tf32(v);
    }
    __syncthreads();

    const int r = tid >> 2;
    const int q = tid & 3;
    float* dst = g_inT1 + (size_t)(b * PLANE + px0 + r) * CPAD1 + q * 40;
    const float* src = &s[r][q * 40];
#pragma unroll
    for (int i = 0; i < 10; i++)
        ((float4*)dst)[i] = ((const float4*)src)[i];
}

// ---------------------------------------------------------------------------
// conv3x3 via mma.sync tf32 (round-12 proven). grid = (HH, 1, B).
// ---------------------------------------------------------------------------
#define CAP 36
#define CONV_AF (128 * CAP)
#define CONV_BF (64 * CAP)
#define CONV_SMEM (2 * (CONV_AF + CONV_BF) * 4)   // 55296 B

template <int CPAD, bool RELU>
__global__ __launch_bounds__(256)
void conv_mma_kernel(const float* __restrict__ inT, const float* __restrict__ wt,
                     const float* __restrict__ bias, float* __restrict__ out) {
    constexpr int CPC = CPAD / 32;
    constexpr int NCH = 9 * CPC;

    extern __shared__ float dsm[];
    const uint32_t sb = (uint32_t)__cvta_generic_to_shared(dsm);
    const uint32_t As_a[2] = {sb, sb + (CONV_AF + CONV_BF) * 4};
    const uint32_t Bs_a[2] = {sb + CONV_AF * 4,
                              sb + (2 * CONV_AF + CONV_BF) * 4};

    const int tid = threadIdx.x;
    const int lid = tid & 31;
    const int wid = tid >> 5;
    const int h   = blockIdx.x;
    const int b   = blockIdx.z;

    auto load_chunk = [&](int lch, int buf) {
        const int tap = lch / CPC;
        const int c0  = (lch % CPC) * 32;
        const int dh  = tap / 3 - 1;
        const int dw  = tap % 3 - 1;
        const int h2  = h + dh;
        const bool vh = (h2 >= 0) && (h2 < HH);
        const int h2c = vh ? h2 : 0;
        const float* inrow = inT + (size_t)(b * PLANE + h2c * WW) * CPAD;
#pragma unroll
        for (int i = 0; i < 4; i++) {
            int seg = tid * 4 + i;
            int row = seg >> 3;
            int s8  = seg & 7;
            int ws  = row + dw;
            bool v  = vh && (ws >= 0) && (ws < WW);
            int wsc = v ? ws : 0;
            cp16z(As_a[buf] + (uint32_t)(row * CAP + s8 * 4) * 4,
                  inrow + (size_t)wsc * CPAD + c0 + s8 * 4, v ? 16u : 0u);
        }
#pragma unroll
        for (int i = 0; i < 2; i++) {
            int seg = tid * 2 + i;
            int o   = seg >> 3;
            int s8  = seg & 7;
            cp16s(Bs_a[buf] + (uint32_t)(o * CAP + s8 * 4) * 4,
                  wt + (size_t)(tap * 64 + o) * CPAD + c0 + s8 * 4);
        }
        CP_COMMIT();
    };

    const int wm = wid & 3;
    const int wn = wid >> 2;
    const int j = lid >> 3, i8 = lid & 7;
    const uint32_t aoff = (uint32_t)(((j & 1) * 8 + i8) * CAP + (j >> 1) * 4) * 4;
    const uint32_t boff = (uint32_t)(((j >> 1) * 8 + i8) * CAP + (j & 1) * 4) * 4;

    float c[2][4][4];
#pragma unroll
    for (int mt = 0; mt < 2; mt++)
#pragma unroll
        for (int nt = 0; nt < 4; nt++)
#pragma unroll
            for (int e = 0; e < 4; e++) c[mt][nt][e] = 0.f;

    load_chunk(0, 0);

    for (int ch = 0; ch < NCH; ch++) {
        const int cur = ch & 1;
        if (ch + 1 < NCH) {
            load_chunk(ch + 1, cur ^ 1);
            cp_wait<1>();
        } else {
            cp_wait<0>();
        }
        __syncthreads();

#pragma unroll
        for (int ks = 0; ks < 4; ks++) {
            const uint32_t kk4 = (uint32_t)(ks * 8) * 4;
            uint32_t a[2][4];
#pragma unroll
            for (int mt = 0; mt < 2; mt++)
                LDMX4(a[mt], As_a[cur] + (uint32_t)((wm * 32 + mt * 16) * CAP) * 4
                             + kk4 + aoff);
            uint32_t bf[2][4];
#pragma unroll
            for (int g = 0; g < 2; g++)
                LDMX4(bf[g], Bs_a[cur] + (uint32_t)((wn * 32 + g * 16) * CAP) * 4
                             + kk4 + boff);
#pragma unroll
            for (int mt = 0; mt < 2; mt++)
#pragma unroll
                for (int nt = 0; nt < 4; nt++)
                    mma_tf32_16n8k8(c[mt][nt], a[mt],
                                    bf[nt >> 1][(nt & 1) * 2],
                                    bf[nt >> 1][(nt & 1) * 2 + 1]);
        }
        __syncthreads();
    }

    float* s_t = dsm;
#pragma unroll
    for (int mt = 0; mt < 2; mt++)
#pragma unroll
        for (int nt = 0; nt < 4; nt++) {
            int px = wm * 32 + mt * 16 + (lid >> 2);
            int o  = wn * 32 + nt * 8 + (lid & 3) * 2;
            s_t[o * 132 + px]           = c[mt][nt][0];
            s_t[(o + 1) * 132 + px]     = c[mt][nt][1];
            s_t[o * 132 + px + 8]       = c[mt][nt][2];
            s_t[(o + 1) * 132 + px + 8] = c[mt][nt][3];
        }
    __syncthreads();
    {
        const int o = tid >> 2;
        const int q = tid & 3;
        const float bv = bias[o];
        float* dst = out + ((size_t)(b * 64 + o) * HH + h) * WW + q * 32;
        const float* src = s_t + o * 132 + q * 32;
#pragma unroll
        for (int i = 0; i < 8; i++) {
            float4 v = ((const float4*)src)[i];
            float4 r = make_float4(v.x + bv, v.y + bv, v.z + bv, v.w + bv);
            if (RELU) {
                r.x = fmaxf(r.x, 0.f); r.y = fmaxf(r.y, 0.f);
                r.z = fmaxf(r.z, 0.f); r.w = fmaxf(r.w, 0.f);
            }
            ((float4*)dst)[i] = r;
        }
    }
}

// ---------------------------------------------------------------------------
// 3x3 SAME conv, CIN=64, small Cout (<=18), optional residual (known-good).
// ---------------------------------------------------------------------------
template <int COUT, bool RES>
__global__ __launch_bounds__(256)
void conv3x3_small_kernel(const float* __restrict__ in, const float* __restrict__ wgt,
                          const float* __restrict__ bias, const float* __restrict__ res,
                          float* __restrict__ out) {
    constexpr int CIN = 64;
    constexpr int CB = 4;
    __shared__ float s_in[CB][10][34];
    __shared__ float s_w[CB][COUT * 9];

    const int tid = threadIdx.x;
    const int wx = tid & 31;
    const int hy = tid >> 5;
    const int w0 = blockIdx.x * 32;
    const int h0 = blockIdx.y * 8;
    const int b  = blockIdx.z;

    float acc[COUT];
#pragma unroll
    for (int o = 0; o < COUT; o++) acc[o] = 0.f;

    for (int c0 = 0; c0 < CIN; c0 += CB) {
        for (int i = tid; i < CB * 10 * 34; i += 256) {
            int cc  = i / 340;
            int rem = i % 340;
            int r   = rem / 34;
            int col = rem % 34;
            int y = h0 - 1 + r;
            int x = w0 - 1 + col;
            float v = 0.f;
            if (y >= 0 && y < HH && x >= 0 && x < WW)
                v = in[((b * CIN + c0 + cc) * HH + y) * WW + x];
            s_in[cc][r][col] = v;
        }
        for (int i = tid; i < CB * COUT * 9; i += 256) {
            int cc  = i / (COUT * 9);
            int rem = i % (COUT * 9);
            int o   = rem / 9;
            int kk  = rem % 9;
            s_w[cc][rem] = wgt[(o * CIN + (c0 + cc)) * 9 + kk];
        }
        __syncthreads();

#pragma unroll
        for (int cc = 0; cc < CB; cc++) {
#pragma unroll
            for (int kh = 0; kh < 3; kh++) {
#pragma unroll
                for (int kw = 0; kw < 3; kw++) {
                    float iv = s_in[cc][hy + kh][wx + kw];
#pragma unroll
                    for (int o = 0; o < COUT; o++)
                        acc[o] += iv * s_w[cc][o * 9 + kh * 3 + kw];
                }
            }
        }
        __syncthreads();
    }

#pragma unroll
    for (int o = 0; o < COUT; o++) {
        float v = acc[o] + bias[o];
        int oi = ((b * COUT + o) * HH + (h0 + hy)) * WW + w0 + wx;
        if (RES) v += res[oi];
        out[oi] = v;
    }
}

// ---------------------------------------------------------------------------
// FUSED deform GEMM: bilinear gather computed in-kernel into the smem A tile
// (no g_sampT intermediate). CTA = 1 row (128 px) x 128 o.
// Phase 0: precompute idx/wt for 128px x 9 taps into smem.
// Per chunk (k=ch>>2, c0=(ch&3)*32): threads compute A[128px][32c] (1px x 16c
// per thread), B via double-buffered cp.async. MMA phase = round-11 proven.
// smem = idx 18432 + wt 18432 + 2*A 36864 + 2*B 36864 = 110592 B.
// grid = (128, 1, B).
// ---------------------------------------------------------------------------
#define AP 36
#define TILE_F (128 * AP)                           // 4608 floats
#define FD_SMEM ((4608 * 2 + 4 * TILE_F) * 4)       // 110592 B

__global__ __launch_bounds__(256)
void dgemm_fused_kernel(const float* __restrict__ feat, const float* __restrict__ offs,
                        const float* __restrict__ dbias) {
    constexpr int NCH = KDIM / 32;                  // 36

    extern __shared__ float dsm[];
    int*   s_idx = (int*)dsm;                       // [px*9+k][4]
    float* s_wt  = dsm + 4608;                      // [px*9+k][4]
    float* A_f[2] = {dsm + 9216,  dsm + 9216 + TILE_F};
    const uint32_t sb = (uint32_t)__cvta_generic_to_shared(dsm);
    const uint32_t Bs_a[2] = {sb + (9216 + 2 * TILE_F) * 4,
                              sb + (9216 + 3 * TILE_F) * 4};
    const uint32_t As_a[2] = {sb + 9216 * 4, sb + (9216 + TILE_F) * 4};

    const int tid = threadIdx.x;
    const int lid = tid & 31;
    const int wid = tid >> 5;
    const int px0 = blockIdx.x * 128;               // = h * WW
    const int b   = blockIdx.z;

    // ---- B producer (cp.async)
    auto load_B = [&](int ch, int buf) {
        const int kc0 = (ch >> 2) * 128 + (ch & 3) * 32;
#pragma unroll
        for (int i = 0; i < 4; i++) {
            int seg = tid * 4 + i;
            int o   = seg >> 3;
            int s   = seg & 7;
            cp16s(Bs_a[buf] + (uint32_t)(o * AP + s * 4) * 4,
                  g_dwt2 + (size_t)o * KDIM + kc0 + s * 4);
        }
        CP_COMMIT();
    };

    load_B(0, 0);

    // ---- Phase 0: precompute bilinear idx/wt (128 px x 9 taps)
    for (int t = tid; t < 1152; t += 256) {
        int px = t / 9;
        int k  = t % 9;
        int g  = px0 + px;
        int h  = g >> 7;
        int w  = g & 127;
        float offy = offs[(size_t)(b * 18 + 2 * k)     * PLANE + g];
        float offx = offs[(size_t)(b * 18 + 2 * k + 1) * PLANE + g];
        float fy = (float)(h + k / 3 - 1) + offy;
        float fx = (float)(w + k % 3 - 1) + offx;
        float y0f = floorf(fy), x0f = floorf(fx);
        float ly = fy - y0f, lx = fx - x0f;
        int y0 = (int)y0f, x0 = (int)x0f;
        float q[4] = {(1.f - ly) * (1.f - lx), (1.f - ly) * lx,
                      ly * (1.f - lx),          ly * lx};
        int ys[4] = {y0, y0, y0 + 1, y0 + 1};
        int xs[4] = {x0, x0 + 1, x0, x0 + 1};
#pragma unroll
        for (int c4 = 0; c4 < 4; c4++) {
            bool valid = (ys[c4] >= 0) && (ys[c4] < HH) && (xs[c4] >= 0) && (xs[c4] < WW);
            s_idx[t * 4 + c4] = valid ? (ys[c4] * WW + xs[c4]) : 0;
            s_wt [t * 4 + c4] = valid ? q[c4] : 0.f;
        }
    }
    __syncthreads();

    // ---- A producer (compute bilinear samples into smem tile)
    const int gpx = tid & 127;
    const int gcg = tid >> 7;           // 0/1 -> 16-channel half
    auto gather_A = [&](int ch, int buf) {
        const int k  = ch >> 2;
        const int c0 = (ch & 3) * 32 + gcg * 16;
        const int4   iv = *(const int4*)&s_idx[(gpx * 9 + k) * 4];
        const float4 qv = *(const float4*)&s_wt[(gpx * 9 + k) * 4];
        const float* fb = feat + (size_t)b * CFEAT * PLANE;
        float* arow = A_f[buf] + gpx * AP + gcg * 16;
#pragma unroll
        for (int j = 0; j < 16; j++) {
            const float* fc = fb + (size_t)(c0 + j) * PLANE;
            arow[j] = to_tf32(qv.x * fc[iv.x] + qv.y * fc[iv.y]
                            + qv.z * fc[iv.z] + qv.w * fc[iv.w]);
        }
    };

    gather_A(0, 0);

    // ---- MMA constants (round-11 proven)
    const int wpx = wid & 1;
    const int wo  = wid >> 1;
    const int j = lid >> 3, i8 = lid & 7;
    const uint32_t aoff = (uint32_t)(((j & 1) * 8 + i8) * AP + (j >> 1) * 4) * 4;
    const uint32_t boff = (uint32_t)(((j >> 1) * 8 + i8) * AP + (j & 1) * 4) * 4;

    float c[4][4][4];
#pragma unroll
    for (int mt = 0; mt < 4; mt++)
#pragma unroll
        for (int nt = 0; nt < 4; nt++)
#pragma unroll
            for (int e = 0; e < 4; e++) c[mt][nt][e] = 0.f;

    for (int ch = 0; ch < NCH; ch++) {
        const int cur = ch & 1;
        if (ch + 1 < NCH) {
            load_B(ch + 1, cur ^ 1);
            cp_wait<1>();
        } else {
            cp_wait<0>();
        }
        __syncthreads();     // A(cur) gathered + B(cur) landed

#pragma unroll
        for (int ks = 0; ks < 4; ks++) {
            const uint32_t kk4 = (uint32_t)(ks * 8) * 4;
            uint32_t a[4][4];
#pragma unroll
            for (int mt = 0; mt < 4; mt++)
                LDMX4(a[mt], As_a[cur] + (uint32_t)((wpx * 64 + mt * 16) * AP) * 4
                             + kk4 + aoff);
            uint32_t bf[2][4];
#pragma unroll
            for (int g = 0; g < 2; g++)
                LDMX4(bf[g], Bs_a[cur] + (uint32_t)((wo * 32 + g * 16) * AP) * 4
                             + kk4 + boff);
#pragma unroll
            for (int mt = 0; mt < 4; mt++)
#pragma unroll
                for (int nt = 0; nt < 4; nt++)
                    mma_tf32_16n8k8(c[mt][nt], a[mt],
                                    bf[nt >> 1][(nt & 1) * 2],
                                    bf[nt >> 1][(nt & 1) * 2 + 1]);
        }
        __syncthreads();     // A(cur) consumed
        if (ch + 1 < NCH) gather_A(ch + 1, cur ^ 1);
    }

    // ---- Epilogue: frags (+bias, tf32) -> smem [px][o] -> g_tmp2T rows
    float* s_t = dsm;
#pragma unroll
    for (int mt = 0; mt < 4; mt++)
#pragma unroll
        for (int nt = 0; nt < 4; nt++) {
            int pxb = wpx * 64 + mt * 16 + (lid >> 2);
            int ob  = wo * 32 + nt * 8 + (lid & 3) * 2;
            float b0 = __ldg(&dbias[ob]);
            float b1 = __ldg(&dbias[ob + 1]);
            s_t[pxb * 132 + ob]           = to_tf32(c[mt][nt][0] + b0);
            s_t[pxb * 132 + ob + 1]       = to_tf32(c[mt][nt][1] + b1);
            s_t[(pxb + 8) * 132 + ob]     = to_tf32(c[mt][nt][2] + b0);
            s_t[(pxb + 8) * 132 + ob + 1] = to_tf32(c[mt][nt][3] + b1);
        }
    __syncthreads();
    {
        const int px = tid >> 1;
        const int hf = tid & 1;
        float* dst = g_tmp2T + (size_t)(b * PLANE + px0 + px) * CFEAT + hf * 64;
        const float* src = s_t + px * 132 + hf * 64;
#pragma unroll
        for (int i = 0; i < 16; i++)
            ((float4*)dst)[i] = ((const float4*)src)[i];
    }
}

// ---------------------------------------------------------------------------
// Launch
// ---------------------------------------------------------------------------
extern "C" void kernel_launch(void* const* d_in, const int* in_sizes, int n_in,
                              void* d_out, int out_size) {
    const float* feat    = (const float*)d_in[0];
    const float* flow    = (const float*)d_in[1];
    const float* off_w1  = (const float*)d_in[2];
    const float* off_b1  = (const float*)d_in[3];
    const float* off_w2  = (const float*)d_in[4];
    const float* off_b2  = (const float*)d_in[5];
    const float* dweight = (const float*)d_in[6];
    const float* dbias   = (const float*)d_in[7];
    const float* fh_w1   = (const float*)d_in[8];
    const float* fh_b1   = (const float*)d_in[9];
    const float* fh_w2   = (const float*)d_in[10];
    const float* fh_b2   = (const float*)d_in[11];
    float* out = (float*)d_out;

    float *tmp1, *off, *tmp2T, *tmp3, *wc1, *wc3, *inT1;
    cudaGetSymbolAddress((void**)&tmp1,  g_tmp1);
    cudaGetSymbolAddress((void**)&off,   g_off);
    cudaGetSymbolAddress((void**)&tmp2T, g_tmp2T);
    cudaGetSymbolAddress((void**)&tmp3,  g_tmp3);
    cudaGetSymbolAddress((void**)&wc1,   g_wc1);
    cudaGetSymbolAddress((void**)&wc3,   g_wc3);
    cudaGetSymbolAddress((void**)&inT1,  g_inT1);

    cudaFuncSetAttribute(dgemm_fused_kernel,
                         cudaFuncAttributeMaxDynamicSharedMemorySize, FD_SMEM);
    cudaFuncSetAttribute(conv_mma_kernel<CPAD1, true>,
                         cudaFuncAttributeMaxDynamicSharedMemorySize, CONV_SMEM);
    cudaFuncSetAttribute(conv_mma_kernel<CFEAT, true>,
                         cudaFuncAttributeMaxDynamicSharedMemorySize, CONV_SMEM);

    // 0. weight transposes (tf32)
    dwt2_transpose_kernel<<<(CFEAT * KDIM + 255) / 256, 256>>>(dweight);
    wcv_transpose_kernel<<<(64 * 130 * 9 + 255) / 256, 256>>>(off_w1, wc1, 130, CPAD1);
    wcv_transpose_kernel<<<(64 * 128 * 9 + 255) / 256, 256>>>(fh_w1, wc3, 128, CFEAT);

    // 1a. transpose concat(feat, flow) -> inT1 [px][160]
    catT_kernel<<<dim3(PLANE / 64, 1, BATCH), 256>>>(feat, flow);

    // 1b. conv1 via mma: 130 -> 64, relu (NCHW out)
    conv_mma_kernel<CPAD1, true><<<dim3(HH, 1, BATCH), 256, CONV_SMEM>>>(
        inT1, wc1, off_b1, tmp1);

    // 2. conv2: 64 -> 18 (offsets)
    conv3x3_small_kernel<18, false><<<dim3(4, 16, BATCH), 256>>>(
        tmp1, off_w2, off_b2, nullptr, off);

    // 3. FUSED gather + deform GEMM -> tmp2T [px][o] (tf32, +bias)
    dgemm_fused_kernel<<<dim3(128, 1, BATCH), 256, FD_SMEM>>>(feat, off, dbias);

    // 4. fh conv1 via mma: 128 -> 64, relu (reads tmp2T directly)
    conv_mma_kernel<CFEAT, true><<<dim3(HH, 1, BATCH), 256, CONV_SMEM>>>(
        tmp2T, wc3, fh_b1, tmp3);

    // 5. fh conv2: 64 -> 2, + flow residual
    conv3x3_small_kernel<2, true><<<dim3(4, 16, BATCH), 256>>>(
        tmp3, fh_w2, fh_b2, flow, out);
}

// round 14
// speedup vs baseline: 1.8955x; 1.1610x over previous
#include <cuda_runtime.h>
#include <math.h>
#include <stdint.h>

// Problem constants
#define HH 128
#define WW 128
#define BATCH 2
#define CFEAT 128
#define PLANE (HH * WW)
#define KDIM (9 * CFEAT)          // 1152

// ---------------------------------------------------------------------------
// cp.async / ldmatrix / mma.sync primitives (sm_80-era, valid on sm_100)
// ---------------------------------------------------------------------------
__device__ __forceinline__ void cp16s(uint32_t smem, const void* gmem) {
    asm volatile("cp.async.cg.shared.global [%0], [%1], 16;" :: "r"(smem), "l"(gmem));
}
__device__ __forceinline__ void cp16z(uint32_t smem, const void* gmem, uint32_t n) {
    asm volatile("cp.async.cg.shared.global [%0], [%1], 16, %2;"
                 :: "r"(smem), "l"(gmem), "r"(n));
}
#define CP_COMMIT() asm volatile("cp.async.commit_group;")
template <int N>
__device__ __forceinline__ void cp_wait() {
    asm volatile("cp.async.wait_group %0;" :: "n"(N));
}

#define LDMX4(r, addr) \
    asm volatile("ldmatrix.sync.aligned.m8n8.x4.shared.b16 {%0,%1,%2,%3}, [%4];" \
                 : "=r"((r)[0]), "=r"((r)[1]), "=r"((r)[2]), "=r"((r)[3]) \
                 : "r"(addr))

__device__ __forceinline__ void mma_tf32_16n8k8(float* c, const uint32_t* a,
                                                uint32_t b0, uint32_t b1) {
    asm volatile(
        "mma.sync.aligned.m16n8k8.row.col.f32.tf32.tf32.f32 "
        "{%0,%1,%2,%3}, {%4,%5,%6,%7}, {%8,%9}, {%0,%1,%2,%3};"
        : "+f"(c[0]), "+f"(c[1]), "+f"(c[2]), "+f"(c[3])
        : "r"(a[0]), "r"(a[1]), "r"(a[2]), "r"(a[3]), "r"(b0), "r"(b1));
}

__device__ __forceinline__ float to_tf32(float x) {
    uint32_t u;
    asm("cvt.rna.tf32.f32 %0, %1;" : "=r"(u) : "f"(x));
    return __uint_as_float(u);
}

// ---------------------------------------------------------------------------
// Scratch (device globals; zero-initialized; no allocation allowed)
// ---------------------------------------------------------------------------
#define CPAD1 160
__device__ float g_tmp1T[BATCH * PLANE * 64];      // conv1 out [b][px][64] tf32
__device__ float g_off  [BATCH * 18 * PLANE];      // offsets NCHW
__device__ float g_tmp2T[BATCH * PLANE * CFEAT];   // deform out [b][px][o] tf32
__device__ float g_tmp3T[BATCH * PLANE * 64];      // fh conv1 out [b][px][64] tf32
__device__ float g_dwt2 [CFEAT * KDIM];            // dweight [o][k*128+c] tf32
__device__ float g_wc1  [9 * 64 * CPAD1];          // off_w1 [tap][o][c_pad] tf32
__device__ float g_wc3  [9 * 64 * CFEAT];          // fh_w1  [tap][o][c] tf32
__device__ float g_wc2  [9 * 32 * 64];             // off_w2 [tap][o32][c] tf32 (pad 0)
__device__ float g_wc4  [9 * 32 * 64];             // fh_w2  [tap][o32][c] tf32 (pad 0)
__device__ float g_inT1 [BATCH * PLANE * CPAD1];   // concat(feat,flow)T tf32

// ---------------------------------------------------------------------------
// Merged weight prep: all 5 transposes in one launch, range-switched.
// ---------------------------------------------------------------------------
#define WP_N1 (CFEAT * KDIM)          // 147456 dwt2
#define WP_N2 (64 * 130 * 9)          //  74880 wc1
#define WP_N3 (64 * 128 * 9)          //  73728 wc3
#define WP_N4 (18 * 64 * 9)           //  10368 wc2
#define WP_N5 (2 * 64 * 9)            //   1152 wc4
#define WP_TOTAL (WP_N1 + WP_N2 + WP_N3 + WP_N4 + WP_N5)

__global__ void wprep_kernel(const float* __restrict__ dw,
                             const float* __restrict__ ow1,
                             const float* __restrict__ fw1,
                             const float* __restrict__ ow2,
                             const float* __restrict__ fw2) {
    int t = blockIdx.x * blockDim.x + threadIdx.x;
    if (t < WP_N1) {
        int o  = t / KDIM;
        int r  = t % KDIM;
        int c  = r / 9;
        int kk = r % 9;
        g_dwt2[(size_t)o * KDIM + kk * 128 + c] = to_tf32(dw[t]);
        return;
    }
    t -= WP_N1;
    if (t < WP_N2) {
        int o  = t / (130 * 9);
        int r  = t % (130 * 9);
        int c  = r / 9;
        int kk = r % 9;
        g_wc1[(kk * 64 + o) * CPAD1 + c] = to_tf32(ow1[t]);
        return;
    }
    t -= WP_N2;
    if (t < WP_N3) {
        int o  = t / (128 * 9);
        int r  = t % (128 * 9);
        int c  = r / 9;
        int kk = r % 9;
        g_wc3[(kk * 64 + o) * CFEAT + c] = to_tf32(fw1[t]);
        return;
    }
    t -= WP_N3;
    if (t < WP_N4) {
        int o  = t / (64 * 9);
        int r  = t % (64 * 9);
        int c  = r / 9;
        int kk = r % 9;
        g_wc2[(kk * 32 + o) * 64 + c] = to_tf32(ow2[t]);
        return;
    }
    t -= WP_N4;
    if (t < WP_N5) {
        int o  = t / (64 * 9);
        int r  = t % (64 * 9);
        int c  = r / 9;
        int kk = r % 9;
        g_wc4[(kk * 32 + o) * 64 + c] = to_tf32(fw2[t]);
    }
}

// ---------------------------------------------------------------------------
// catT: concat(feat[128], flow[2]) NCHW -> g_inT1[b][px][160] (tf32, zero pad)
// ---------------------------------------------------------------------------
__global__ __launch_bounds__(256)
void catT_kernel(const float* __restrict__ feat, const float* __restrict__ flow) {
    __shared__ float s[64][164];
    const int tid = threadIdx.x;
    const int pxt = tid & 63;
    const int cg  = tid >> 6;
    const int b   = blockIdx.z;
    const int px0 = blockIdx.x * 64;
    const int px  = px0 + pxt;

#pragma unroll 8
    for (int j = 0; j < 40; j++) {
        int c = cg * 40 + j;
        float v = 0.f;
        if (c < 128)      v = feat[(size_t)(b * 128 + c) * PLANE + px];
        else if (c < 130) v = flow[(size_t)(b * 2 + (c - 128)) * PLANE + px];
        s[pxt][c] = to_tf32(v);
    }
    __syncthreads();

    const int r = tid >> 2;
    const int q = tid & 3;
    float* dst = g_inT1 + (size_t)(b * PLANE + px0 + r) * CPAD1 + q * 40;
    const float* src = &s[r][q * 40];
#pragma unroll
    for (int i = 0; i < 10; i++)
        ((float4*)dst)[i] = ((const float4*)src)[i];
}

// ---------------------------------------------------------------------------
// conv3x3 via mma.sync tf32 (proven); epilogue now writes TRANSPOSED tf32
// outT[b][px][64] (+bias, relu). grid = (HH, 1, B).
// ---------------------------------------------------------------------------
#define CAP 36
#define CONV_AF (128 * CAP)
#define CONV_BF (64 * CAP)
#define CONV_SMEM (2 * (CONV_AF + CONV_BF) * 4)   // 55296 B

template <int CPAD, bool RELU>
__global__ __launch_bounds__(256)
void conv_mma_kernel(const float* __restrict__ inT, const float* __restrict__ wt,
                     const float* __restrict__ bias, float* __restrict__ outT) {
    constexpr int CPC = CPAD / 32;
    constexpr int NCH = 9 * CPC;

    extern __shared__ float dsm[];
    const uint32_t sb = (uint32_t)__cvta_generic_to_shared(dsm);
    const uint32_t As_a[2] = {sb, sb + (CONV_AF + CONV_BF) * 4};
    const uint32_t Bs_a[2] = {sb + CONV_AF * 4,
                              sb + (2 * CONV_AF + CONV_BF) * 4};

    const int tid = threadIdx.x;
    const int lid = tid & 31;
    const int wid = tid >> 5;
    const int h   = blockIdx.x;
    const int b   = blockIdx.z;

    auto load_chunk = [&](int lch, int buf) {
        const int tap = lch / CPC;
        const int c0  = (lch % CPC) * 32;
        const int dh  = tap / 3 - 1;
        const int dw  = tap % 3 - 1;
        const int h2  = h + dh;
        const bool vh = (h2 >= 0) && (h2 < HH);
        const int h2c = vh ? h2 : 0;
        const float* inrow = inT + (size_t)(b * PLANE + h2c * WW) * CPAD;
#pragma unroll
        for (int i = 0; i < 4; i++) {
            int seg = tid * 4 + i;
            int row = seg >> 3;
            int s8  = seg & 7;
            int ws  = row + dw;
            bool v  = vh && (ws >= 0) && (ws < WW);
            int wsc = v ? ws : 0;
            cp16z(As_a[buf] + (uint32_t)(row * CAP + s8 * 4) * 4,
                  inrow + (size_t)wsc * CPAD + c0 + s8 * 4, v ? 16u : 0u);
        }
#pragma unroll
        for (int i = 0; i < 2; i++) {
            int seg = tid * 2 + i;
            int o   = seg >> 3;
            int s8  = seg & 7;
            cp16s(Bs_a[buf] + (uint32_t)(o * CAP + s8 * 4) * 4,
                  wt + (size_t)(tap * 64 + o) * CPAD + c0 + s8 * 4);
        }
        CP_COMMIT();
    };

    const int wm = wid & 3;
    const int wn = wid >> 2;
    const int j = lid >> 3, i8 = lid & 7;
    const uint32_t aoff = (uint32_t)(((j & 1) * 8 + i8) * CAP + (j >> 1) * 4) * 4;
    const uint32_t boff = (uint32_t)(((j >> 1) * 8 + i8) * CAP + (j & 1) * 4) * 4;

    float c[2][4][4];
#pragma unroll
    for (int mt = 0; mt < 2; mt++)
#pragma unroll
        for (int nt = 0; nt < 4; nt++)
#pragma unroll
            for (int e = 0; e < 4; e++) c[mt][nt][e] = 0.f;

    load_chunk(0, 0);

    for (int ch = 0; ch < NCH; ch++) {
        const int cur = ch & 1;
        if (ch + 1 < NCH) {
            load_chunk(ch + 1, cur ^ 1);
            cp_wait<1>();
        } else {
            cp_wait<0>();
        }
        __syncthreads();

#pragma unroll
        for (int ks = 0; ks < 4; ks++) {
            const uint32_t kk4 = (uint32_t)(ks * 8) * 4;
            uint32_t a[2][4];
#pragma unroll
            for (int mt = 0; mt < 2; mt++)
                LDMX4(a[mt], As_a[cur] + (uint32_t)((wm * 32 + mt * 16) * CAP) * 4
                             + kk4 + aoff);
            uint32_t bf[2][4];
#pragma unroll
            for (int g = 0; g < 2; g++)
                LDMX4(bf[g], Bs_a[cur] + (uint32_t)((wn * 32 + g * 16) * CAP) * 4
                             + kk4 + boff);
#pragma unroll
            for (int mt = 0; mt < 2; mt++)
#pragma unroll
                for (int nt = 0; nt < 4; nt++)
                    mma_tf32_16n8k8(c[mt][nt], a[mt],
                                    bf[nt >> 1][(nt & 1) * 2],
                                    bf[nt >> 1][(nt & 1) * 2 + 1]);
        }
        __syncthreads();
    }

    // Epilogue: frags (+bias, relu, tf32) -> smem [px][o] (stride 68) -> outT
    float* s_t = dsm;
#pragma unroll
    for (int mt = 0; mt < 2; mt++)
#pragma unroll
        for (int nt = 0; nt < 4; nt++) {
            int px = wm * 32 + mt * 16 + (lid >> 2);
            int o  = wn * 32 + nt * 8 + (lid & 3) * 2;
            float b0 = __ldg(&bias[o]);
            float b1 = __ldg(&bias[o + 1]);
            float v0 = c[mt][nt][0] + b0;
            float v1 = c[mt][nt][1] + b1;
            float v2 = c[mt][nt][2] + b0;
            float v3 = c[mt][nt][3] + b1;
            if (RELU) {
                v0 = fmaxf(v0, 0.f); v1 = fmaxf(v1, 0.f);
                v2 = fmaxf(v2, 0.f); v3 = fmaxf(v3, 0.f);
            }
            s_t[px * 68 + o]           = to_tf32(v0);
            s_t[px * 68 + o + 1]       = to_tf32(v1);
            s_t[(px + 8) * 68 + o]     = to_tf32(v2);
            s_t[(px + 8) * 68 + o + 1] = to_tf32(v3);
        }
    __syncthreads();
    {
        const int px = tid >> 1;
        const int hf = tid & 1;
        float* dst = outT + (size_t)(b * PLANE + h * WW + px) * 64 + hf * 32;
        const float* src = s_t + px * 68 + hf * 32;
#pragma unroll
        for (int i = 0; i < 8; i++)
            ((float4*)dst)[i] = ((const float4*)src)[i];
    }
}

// ---------------------------------------------------------------------------
// Small conv3x3 via mma: CIN=64, COUT<=32 (padded to 32). CTA = 1 row x 32o.
// 8 warps x 16px. Input: inT [b][px][64] tf32. Weights: wsm [tap][32][64].
// Epilogue: NCHW out (+bias, optional flow residual). grid = (HH, 1, B).
// ---------------------------------------------------------------------------
#define SC_AF (128 * CAP)              // A tile floats (stride 36)
#define SC_BF (32 * CAP)
#define SC_SMEM (2 * (SC_AF + SC_BF) * 4)   // 46080 B

template <int COUT, bool RES>
__global__ __launch_bounds__(256)
void conv_mma_small_kernel(const float* __restrict__ inT, const float* __restrict__ wsm,
                           const float* __restrict__ bias, const float* __restrict__ res,
                           float* __restrict__ out) {
    constexpr int NCH = 18;            // 9 taps x 2 c-chunks

    extern __shared__ float dsm[];
    const uint32_t sb = (uint32_t)__cvta_generic_to_shared(dsm);
    const uint32_t As_a[2] = {sb, sb + (SC_AF + SC_BF) * 4};
    const uint32_t Bs_a[2] = {sb + SC_AF * 4, sb + (2 * SC_AF + SC_BF) * 4};

    const int tid = threadIdx.x;
    const int lid = tid & 31;
    const int wid = tid >> 5;
    const int h   = blockIdx.x;
    const int b   = blockIdx.z;

    auto load_chunk = [&](int lch, int buf) {
        const int tap = lch >> 1;
        const int c0  = (lch & 1) * 32;
        const int dh  = tap / 3 - 1;
        const int dw  = tap % 3 - 1;
        const int h2  = h + dh;
        const bool vh = (h2 >= 0) && (h2 < HH);
        const int h2c = vh ? h2 : 0;
        const float* inrow = inT + (size_t)(b * PLANE + h2c * WW) * 64;
        // A: 1024 segs, 4/thread
#pragma unroll
        for (int i = 0; i < 4; i++) {
            int seg = tid * 4 + i;
            int row = seg >> 3;
            int s8  = seg & 7;
            int ws  = row + dw;
            bool v  = vh && (ws >= 0) && (ws < WW);
            int wsc = v ? ws : 0;
            cp16z(As_a[buf] + (uint32_t)(row * CAP + s8 * 4) * 4,
                  inrow + (size_t)wsc * 64 + c0 + s8 * 4, v ? 16u : 0u);
        }
        // B: 256 segs, 1/thread
        {
            int o  = tid >> 3;
            int s8 = tid & 7;
            cp16s(Bs_a[buf] + (uint32_t)(o * CAP + s8 * 4) * 4,
                  wsm + (size_t)(tap * 32 + o) * 64 + c0 + s8 * 4);
        }
        CP_COMMIT();
    };

    const int j = lid >> 3, i8 = lid & 7;
    const uint32_t aoff = (uint32_t)(((j & 1) * 8 + i8) * CAP + (j >> 1) * 4) * 4;
    const uint32_t boff = (uint32_t)(((j >> 1) * 8 + i8) * CAP + (j & 1) * 4) * 4;

    float c[4][4];
#pragma unroll
    for (int nt = 0; nt < 4; nt++)
#pragma unroll
        for (int e = 0; e < 4; e++) c[nt][e] = 0.f;

    load_chunk(0, 0);

    for (int ch = 0; ch < NCH; ch++) {
        const int cur = ch & 1;
        if (ch + 1 < NCH) {
            load_chunk(ch + 1, cur ^ 1);
            cp_wait<1>();
        } else {
            cp_wait<0>();
        }
        __syncthreads();

#pragma unroll
        for (int ks = 0; ks < 4; ks++) {
            const uint32_t kk4 = (uint32_t)(ks * 8) * 4;
            uint32_t a[4];
            LDMX4(a, As_a[cur] + (uint32_t)((wid * 16) * CAP) * 4 + kk4 + aoff);
            uint32_t bf[2][4];
#pragma unroll
            for (int g = 0; g < 2; g++)
                LDMX4(bf[g], Bs_a[cur] + (uint32_t)((g * 16) * CAP) * 4 + kk4 + boff);
#pragma unroll
            for (int nt = 0; nt < 4; nt++)
                mma_tf32_16n8k8(c[nt], a,
                                bf[nt >> 1][(nt & 1) * 2],
                                bf[nt >> 1][(nt & 1) * 2 + 1]);
        }
        __syncthreads();
    }

    // Epilogue: frags -> smem [px][o] (stride 34) -> NCHW (+bias, opt residual)
    float* s_t = dsm;
#pragma unroll
    for (int nt = 0; nt < 4; nt++) {
        int px = wid * 16 + (lid >> 2);
        int o  = nt * 8 + (lid & 3) * 2;
        s_t[px * 34 + o]           = c[nt][0];
        s_t[px * 34 + o + 1]       = c[nt][1];
        s_t[(px + 8) * 34 + o]     = c[nt][2];
        s_t[(px + 8) * 34 + o + 1] = c[nt][3];
    }
    __syncthreads();
    for (int idx = tid; idx < COUT * 128; idx += 256) {
        int o  = idx >> 7;
        int px = idx & 127;
        float v = s_t[px * 34 + o] + __ldg(&bias[o]);
        size_t gi = (size_t)(b * COUT + o) * PLANE + h * WW + px;
        if (RES) v += res[gi];
        out[gi] = v;
    }
}

// ---------------------------------------------------------------------------
// FUSED deform GEMM (round-13 proven). grid = (128, 1, B).
// ---------------------------------------------------------------------------
#define AP 36
#define TILE_F (128 * AP)                           // 4608 floats
#define FD_SMEM ((4608 * 2 + 4 * TILE_F) * 4)       // 110592 B

__global__ __launch_bounds__(256)
void dgemm_fused_kernel(const float* __restrict__ feat, const float* __restrict__ offs,
                        const float* __restrict__ dbias) {
    constexpr int NCH = KDIM / 32;                  // 36

    extern __shared__ float dsm[];
    int*   s_idx = (int*)dsm;
    float* s_wt  = dsm + 4608;
    float* A_f[2] = {dsm + 9216,  dsm + 9216 + TILE_F};
    const uint32_t sb = (uint32_t)__cvta_generic_to_shared(dsm);
    const uint32_t Bs_a[2] = {sb + (9216 + 2 * TILE_F) * 4,
                              sb + (9216 + 3 * TILE_F) * 4};
    const uint32_t As_a[2] = {sb + 9216 * 4, sb + (9216 + TILE_F) * 4};

    const int tid = threadIdx.x;
    const int lid = tid & 31;
    const int wid = tid >> 5;
    const int px0 = blockIdx.x * 128;
    const int b   = blockIdx.z;

    auto load_B = [&](int ch, int buf) {
        const int kc0 = (ch >> 2) * 128 + (ch & 3) * 32;
#pragma unroll
        for (int i = 0; i < 4; i++) {
            int seg = tid * 4 + i;
            int o   = seg >> 3;
            int s   = seg & 7;
            cp16s(Bs_a[buf] + (uint32_t)(o * AP + s * 4) * 4,
                  g_dwt2 + (size_t)o * KDIM + kc0 + s * 4);
        }
        CP_COMMIT();
    };

    load_B(0, 0);

    for (int t = tid; t < 1152; t += 256) {
        int px = t / 9;
        int k  = t % 9;
        int g  = px0 + px;
        int h  = g >> 7;
        int w  = g & 127;
        float offy = offs[(size_t)(b * 18 + 2 * k)     * PLANE + g];
        float offx = offs[(size_t)(b * 18 + 2 * k + 1) * PLANE + g];
        float fy = (float)(h + k / 3 - 1) + offy;
        float fx = (float)(w + k % 3 - 1) + offx;
        float y0f = floorf(fy), x0f = floorf(fx);
        float ly = fy - y0f, lx = fx - x0f;
        int y0 = (int)y0f, x0 = (int)x0f;
        float q[4] = {(1.f - ly) * (1.f - lx), (1.f - ly) * lx,
                      ly * (1.f - lx),          ly * lx};
        int ys[4] = {y0, y0, y0 + 1, y0 + 1};
        int xs[4] = {x0, x0 + 1, x0, x0 + 1};
#pragma unroll
        for (int c4 = 0; c4 < 4; c4++) {
            bool valid = (ys[c4] >= 0) && (ys[c4] < HH) && (xs[c4] >= 0) && (xs[c4] < WW);
            s_idx[t * 4 + c4] = valid ? (ys[c4] * WW + xs[c4]) : 0;
            s_wt [t * 4 + c4] = valid ? q[c4] : 0.f;
        }
    }
    __syncthreads();

    const int gpx = tid & 127;
    const int gcg = tid >> 7;
    auto gather_A = [&](int ch, int buf) {
        const int k  = ch >> 2;
        const int c0 = (ch & 3) * 32 + gcg * 16;
        const int4   iv = *(const int4*)&s_idx[(gpx * 9 + k) * 4];
        const float4 qv = *(const float4*)&s_wt[(gpx * 9 + k) * 4];
        const float* fb = feat + (size_t)b * CFEAT * PLANE;
        float* arow = A_f[buf] + gpx * AP + gcg * 16;
#pragma unroll
        for (int j = 0; j < 16; j++) {
            const float* fc = fb + (size_t)(c0 + j) * PLANE;
            arow[j] = to_tf32(qv.x * fc[iv.x] + qv.y * fc[iv.y]
                            + qv.z * fc[iv.z] + qv.w * fc[iv.w]);
        }
    };

    gather_A(0, 0);

    const int wpx = wid & 1;
    const int wo  = wid >> 1;
    const int j = lid >> 3, i8 = lid & 7;
    const uint32_t aoff = (uint32_t)(((j & 1) * 8 + i8) * AP + (j >> 1) * 4) * 4;
    const uint32_t boff = (uint32_t)(((j >> 1) * 8 + i8) * AP + (j & 1) * 4) * 4;

    float c[4][4][4];
#pragma unroll
    for (int mt = 0; mt < 4; mt++)
#pragma unroll
        for (int nt = 0; nt < 4; nt++)
#pragma unroll
            for (int e = 0; e < 4; e++) c[mt][nt][e] = 0.f;

    for (int ch = 0; ch < NCH; ch++) {
        const int cur = ch & 1;
        if (ch + 1 < NCH) {
            load_B(ch + 1, cur ^ 1);
            cp_wait<1>();
        } else {
            cp_wait<0>();
        }
        __syncthreads();

#pragma unroll
        for (int ks = 0; ks < 4; ks++) {
            const uint32_t kk4 = (uint32_t)(ks * 8) * 4;
            uint32_t a[4][4];
#pragma unroll
            for (int mt = 0; mt < 4; mt++)
                LDMX4(a[mt], As_a[cur] + (uint32_t)((wpx * 64 + mt * 16) * AP) * 4
                             + kk4 + aoff);
            uint32_t bf[2][4];
#pragma unroll
            for (int g = 0; g < 2; g++)
                LDMX4(bf[g], Bs_a[cur] + (uint32_t)((wo * 32 + g * 16) * AP) * 4
                             + kk4 + boff);
#pragma unroll
            for (int mt = 0; mt < 4; mt++)
#pragma unroll
                for (int nt = 0; nt < 4; nt++)
                    mma_tf32_16n8k8(c[mt][nt], a[mt],
                                    bf[nt >> 1][(nt & 1) * 2],
                                    bf[nt >> 1][(nt & 1) * 2 + 1]);
        }
        __syncthreads();
        if (ch + 1 < NCH) gather_A(ch + 1, cur ^ 1);
    }

    float* s_t = dsm;
#pragma unroll
    for (int mt = 0; mt < 4; mt++)
#pragma unroll
        for (int nt = 0; nt < 4; nt++) {
            int pxb = wpx * 64 + mt * 16 + (lid >> 2);
            int ob  = wo * 32 + nt * 8 + (lid & 3) * 2;
            float b0 = __ldg(&dbias[ob]);
            float b1 = __ldg(&dbias[ob + 1]);
            s_t[pxb * 132 + ob]           = to_tf32(c[mt][nt][0] + b0);
            s_t[pxb * 132 + ob + 1]       = to_tf32(c[mt][nt][1] + b1);
            s_t[(pxb + 8) * 132 + ob]     = to_tf32(c[mt][nt][2] + b0);
            s_t[(pxb + 8) * 132 + ob + 1] = to_tf32(c[mt][nt][3] + b1);
        }
    __syncthreads();
    {
        const int px = tid >> 1;
        const int hf = tid & 1;
        float* dst = g_tmp2T + (size_t)(b * PLANE + px0 + px) * CFEAT + hf * 64;
        const float* src = s_t + px * 132 + hf * 64;
#pragma unroll
        for (int i = 0; i < 16; i++)
            ((float4*)dst)[i] = ((const float4*)src)[i];
    }
}

// ---------------------------------------------------------------------------
// Launch
// ---------------------------------------------------------------------------
extern "C" void kernel_launch(void* const* d_in, const int* in_sizes, int n_in,
                              void* d_out, int out_size) {
    const float* feat    = (const float*)d_in[0];
    const float* flow    = (const float*)d_in[1];
    const float* off_w1  = (const float*)d_in[2];
    const float* off_b1  = (const float*)d_in[3];
    const float* off_w2  = (const float*)d_in[4];
    const float* off_b2  = (const float*)d_in[5];
    const float* dweight = (const float*)d_in[6];
    const float* dbias   = (const float*)d_in[7];
    const float* fh_w1   = (const float*)d_in[8];
    const float* fh_b1   = (const float*)d_in[9];
    const float* fh_w2   = (const float*)d_in[10];
    const float* fh_b2   = (const float*)d_in[11];
    float* out = (float*)d_out;

    float *tmp1T, *off, *tmp2T, *tmp3T, *wc1, *wc3, *wc2, *wc4, *inT1;
    cudaGetSymbolAddress((void**)&tmp1T, g_tmp1T);
    cudaGetSymbolAddress((void**)&off,   g_off);
    cudaGetSymbolAddress((void**)&tmp2T, g_tmp2T);
    cudaGetSymbolAddress((void**)&tmp3T, g_tmp3T);
    cudaGetSymbolAddress((void**)&wc1,   g_wc1);
    cudaGetSymbolAddress((void**)&wc3,   g_wc3);
    cudaGetSymbolAddress((void**)&wc2,   g_wc2);
    cudaGetSymbolAddress((void**)&wc4,   g_wc4);
    cudaGetSymbolAddress((void**)&inT1,  g_inT1);

    cudaFuncSetAttribute(dgemm_fused_kernel,
                         cudaFuncAttributeMaxDynamicSharedMemorySize, FD_SMEM);
    cudaFuncSetAttribute(conv_mma_kernel<CPAD1, true>,
                         cudaFuncAttributeMaxDynamicSharedMemorySize, CONV_SMEM);
    cudaFuncSetAttribute(conv_mma_kernel<CFEAT, true>,
                         cudaFuncAttributeMaxDynamicSharedMemorySize, CONV_SMEM);
    cudaFuncSetAttribute(conv_mma_small_kernel<18, false>,
                         cudaFuncAttributeMaxDynamicSharedMemorySize, SC_SMEM);
    cudaFuncSetAttribute(conv_mma_small_kernel<2, true>,
                         cudaFuncAttributeMaxDynamicSharedMemorySize, SC_SMEM);

    // 0. all weight transposes (one launch)
    wprep_kernel<<<(WP_TOTAL + 255) / 256, 256>>>(dweight, off_w1, fh_w1,
                                                  off_w2, fh_w2);

    // 1a. transpose concat(feat, flow) -> inT1 [px][160]
    catT_kernel<<<dim3(PLANE / 64, 1, BATCH), 256>>>(feat, flow);

    // 1b. conv1 via mma: 130 -> 64, relu -> tmp1T [px][64] tf32
    conv_mma_kernel<CPAD1, true><<<dim3(HH, 1, BATCH), 256, CONV_SMEM>>>(
        inT1, wc1, off_b1, tmp1T);

    // 2. conv2 via mma: 64 -> 18 -> offsets NCHW
    conv_mma_small_kernel<18, false><<<dim3(HH, 1, BATCH), 256, SC_SMEM>>>(
        tmp1T, wc2, off_b2, nullptr, off);

    // 3. FUSED gather + deform GEMM -> tmp2T [px][o] (tf32, +bias)
    dgemm_fused_kernel<<<dim3(128, 1, BATCH), 256, FD_SMEM>>>(feat, off, dbias);

    // 4. fh conv1 via mma: 128 -> 64, relu -> tmp3T [px][64] tf32
    conv_mma_kernel<CFEAT, true><<<dim3(HH, 1, BATCH), 256, CONV_SMEM>>>(
        tmp2T, wc3, fh_b1, tmp3T);

    // 5. fh conv2 via mma: 64 -> 2, + flow residual -> out NCHW
    conv_mma_small_kernel<2, true><<<dim3(HH, 1, BATCH), 256, SC_SMEM>>>(
        tmp3T, wc4, fh_b2, flow, out);
}